// round 2
// baseline (speedup 1.0000x reference)
#include <cuda_runtime.h>
#include <math.h>

#define SEQ    2048
#define HIDDEN 4096
#define NH     32
#define HD     128
#define NKV    8
#define QKVD   6144   // (NH + 2*NKV) * HD
#define KOFF   4096   // NH*HD
#define VOFF   5120   // NH*HD + NKV*HD

// Scratch (allocation-free rule: __device__ globals)
__device__ float g_qkv[SEQ * QKVD];    // 50.3 MB
__device__ float g_attn[SEQ * HIDDEN]; // 33.5 MB

// ---------------------------------------------------------------------------
// SGEMM: C[M,N] = A[M,K] @ B[K,N], row-major, BM=BN=128, BK=8, 256 threads,
// 8x8 per-thread tile, float4 loads, A stored transposed in smem.
// ---------------------------------------------------------------------------
__global__ __launch_bounds__(256) void sgemm_kernel(
    const float* __restrict__ A, const float* __restrict__ B,
    float* __restrict__ C, int M, int N, int K)
{
    __shared__ float As[8][132];  // padded: conflict-free transposed stores
    __shared__ float Bs[8][128];

    const int tid = threadIdx.x;
    const int tx = tid & 15;       // 16 col groups
    const int ty = tid >> 4;       // 16 row groups
    const int rowBase = blockIdx.y * 128;
    const int colBase = blockIdx.x * 128;

    const int arow  = tid >> 1;        // 0..127
    const int acol4 = (tid & 1) * 4;   // 0 or 4
    const int brow  = tid >> 5;        // 0..7
    const int bcol  = (tid & 31) << 2; // 0..124

    float acc[8][8];
#pragma unroll
    for (int i = 0; i < 8; i++)
#pragma unroll
        for (int j = 0; j < 8; j++) acc[i][j] = 0.f;

    for (int k0 = 0; k0 < K; k0 += 8) {
        float4 a = *(const float4*)&A[(rowBase + arow) * K + k0 + acol4];
        float4 b = *(const float4*)&B[(k0 + brow) * N + colBase + bcol];
        As[acol4 + 0][arow] = a.x;
        As[acol4 + 1][arow] = a.y;
        As[acol4 + 2][arow] = a.z;
        As[acol4 + 3][arow] = a.w;
        *(float4*)&Bs[brow][bcol] = b;
        __syncthreads();

#pragma unroll
        for (int k = 0; k < 8; k++) {
            float4 a0 = *(const float4*)&As[k][ty * 8];
            float4 a1 = *(const float4*)&As[k][ty * 8 + 4];
            float4 b0 = *(const float4*)&Bs[k][tx * 8];
            float4 b1 = *(const float4*)&Bs[k][tx * 8 + 4];
            float av[8] = {a0.x, a0.y, a0.z, a0.w, a1.x, a1.y, a1.z, a1.w};
            float bv[8] = {b0.x, b0.y, b0.z, b0.w, b1.x, b1.y, b1.z, b1.w};
#pragma unroll
            for (int i = 0; i < 8; i++)
#pragma unroll
                for (int j = 0; j < 8; j++)
                    acc[i][j] = fmaf(av[i], bv[j], acc[i][j]);
        }
        __syncthreads();
    }

#pragma unroll
    for (int i = 0; i < 8; i++) {
        int row = rowBase + ty * 8 + i;
        float4 c0 = make_float4(acc[i][0], acc[i][1], acc[i][2], acc[i][3]);
        float4 c1 = make_float4(acc[i][4], acc[i][5], acc[i][6], acc[i][7]);
        *(float4*)&C[row * N + colBase + tx * 8]     = c0;
        *(float4*)&C[row * N + colBase + tx * 8 + 4] = c1;
    }
}

// ---------------------------------------------------------------------------
// RoPE in-place on q (32 heads) and k (8 heads), first 64 dims of each head.
// One thread per (s, head, j) pair; half = 32.
// positions buffer may be int32 (JAX x64-disabled) or int64; sniff layout:
// as int32 words, word[1] == 0 iff little-endian int64 (high half of pos 0).
// ---------------------------------------------------------------------------
__global__ __launch_bounds__(256) void rope_kernel(const int* __restrict__ pos32)
{
    int idx = blockIdx.x * blockDim.x + threadIdx.x;
    if (idx >= SEQ * 40 * 32) return;
    int j = idx & 31;
    int t = idx >> 5;
    int h = t % 40;
    int s = t / 40;

    bool is64 = (pos32[1] == 0);
    int posi = is64 ? pos32[2 * s] : pos32[s];

    float pos = (float)posi;
    float inv_freq = 1.0f / powf(10000.0f, (float)j * (1.0f / 32.0f));
    float f = pos * inv_freq;
    float cs, sn;
    sincosf(f, &sn, &cs);

    int base = s * QKVD + ((h < 32) ? h * HD : KOFF + (h - 32) * HD);
    float x1 = g_qkv[base + j];
    float x2 = g_qkv[base + 32 + j];
    g_qkv[base + j]      = x1 * cs - x2 * sn;
    g_qkv[base + 32 + j] = x2 * cs + x1 * sn;
}

// ---------------------------------------------------------------------------
// Flash attention: block = (q-tile of 64, head). 256 threads = 8 warps,
// each warp owns 8 query rows; lane = key within 32-wide KV tile.
// K stored transposed (d4-major) in smem for conflict-free lane-per-key dots.
// Online softmax, causal mask, GQA (kv head = h/4).
// ---------------------------------------------------------------------------
__global__ __launch_bounds__(256) void attn_kernel()
{
    extern __shared__ float4 smem4[];
    float4* qs4 = smem4;            // [64][32]  Q tile (row-major, f4 chunks)
    float4* kt4 = qs4 + 64 * 32;    // [32][33]  K tile transposed: [d4][key], padded
    float4* vs4 = kt4 + 32 * 33;    // [32][32]  V tile: [key][d4]

    const int tid  = threadIdx.x;
    const int lane = tid & 31;
    const int warp = tid >> 5;
    const int qt   = gridDim.x - 1 - blockIdx.x;  // heavy tiles first
    const int h    = blockIdx.y;
    const int kvh  = h >> 2;
    const int qbase = qt * 64;

    // Load Q tile (RoPE already applied)
    for (int i = tid; i < 64 * 32; i += 256) {
        int row = i >> 5, d4 = i & 31;
        qs4[i] = *(const float4*)&g_qkv[(qbase + row) * QKVD + h * HD + d4 * 4];
    }
    __syncthreads();

    float m[8], l[8];
    float4 O[8];
#pragma unroll
    for (int r = 0; r < 8; r++) {
        m[r] = -INFINITY; l[r] = 0.f;
        O[r] = make_float4(0.f, 0.f, 0.f, 0.f);
    }

    const float scale = 0.088388347648318447f;  // 1/sqrt(128)
    const int ntiles = (qbase + 63) / 32 + 1;

    for (int t = 0; t < ntiles; t++) {
        const int kb = t * 32;
        // Load K (transposed) and V tiles
        for (int i = tid; i < 32 * 32; i += 256) {
            int key = i >> 5, d4 = i & 31;
            const float* kp = &g_qkv[(kb + key) * QKVD + KOFF + kvh * HD + d4 * 4];
            const float* vp = &g_qkv[(kb + key) * QKVD + VOFF + kvh * HD + d4 * 4];
            kt4[d4 * 33 + key] = *(const float4*)kp;
            vs4[key * 32 + d4] = *(const float4*)vp;
        }
        __syncthreads();

        // Scores: s[r] = q_row . k_lane
        float s[8];
#pragma unroll
        for (int r = 0; r < 8; r++) s[r] = 0.f;
#pragma unroll 4
        for (int d4 = 0; d4 < 32; d4++) {
            float4 kk = kt4[d4 * 33 + lane];
#pragma unroll
            for (int r = 0; r < 8; r++) {
                float4 q = qs4[(warp * 8 + r) * 32 + d4];
                s[r] += q.x * kk.x + q.y * kk.y + q.z * kk.z + q.w * kk.w;
            }
        }

        // Online softmax (per row, across 32 lanes = 32 keys)
        const int kg = kb + lane;
        float p[8];
#pragma unroll
        for (int r = 0; r < 8; r++) {
            int qg = qbase + warp * 8 + r;
            float sv = (kg <= qg) ? s[r] * scale : -INFINITY;
            float mt = sv;
#pragma unroll
            for (int o = 16; o; o >>= 1)
                mt = fmaxf(mt, __shfl_xor_sync(0xffffffffu, mt, o));
            float mn = fmaxf(m[r], mt);
            float pv = expf(sv - mn);       // expf(-inf)=0 handles mask & init
            float ls = pv;
#pragma unroll
            for (int o = 16; o; o >>= 1)
                ls += __shfl_xor_sync(0xffffffffu, ls, o);
            float alpha = expf(m[r] - mn);  // 0 on first valid tile
            l[r] = l[r] * alpha + ls;
            m[r] = mn;
            O[r].x *= alpha; O[r].y *= alpha; O[r].z *= alpha; O[r].w *= alpha;
            p[r] = pv;
        }

        // O += p @ V   (lane owns d = lane*4..lane*4+3)
#pragma unroll 4
        for (int k = 0; k < 32; k++) {
            float4 v = vs4[k * 32 + lane];
#pragma unroll
            for (int r = 0; r < 8; r++) {
                float pk = __shfl_sync(0xffffffffu, p[r], k);
                O[r].x += pk * v.x; O[r].y += pk * v.y;
                O[r].z += pk * v.z; O[r].w += pk * v.w;
            }
        }
        __syncthreads();
    }

    // Normalize and write
#pragma unroll
    for (int r = 0; r < 8; r++) {
        int sg = qbase + warp * 8 + r;
        float inv = 1.0f / l[r];
        float4 o = make_float4(O[r].x * inv, O[r].y * inv, O[r].z * inv, O[r].w * inv);
        *(float4*)&g_attn[sg * HIDDEN + h * HD + lane * 4] = o;
    }
}

// ---------------------------------------------------------------------------
extern "C" void kernel_launch(void* const* d_in, const int* in_sizes, int n_in,
                              void* d_out, int out_size)
{
    const float* hidden    = (const float*)d_in[0];
    const float* Wqkv      = (const float*)d_in[1];
    const float* Wo        = (const float*)d_in[2];
    const int*   positions = (const int*)d_in[3];   // int32 or int64 words; sniffed on device
    float*       out       = (float*)d_out;

    float *qkv_ptr, *attn_ptr;
    cudaGetSymbolAddress((void**)&qkv_ptr, g_qkv);
    cudaGetSymbolAddress((void**)&attn_ptr, g_attn);

    const int attn_smem = (64 * 32 + 32 * 33 + 32 * 32) * 16;  // 66048 B
    cudaFuncSetAttribute(attn_kernel, cudaFuncAttributeMaxDynamicSharedMemorySize, attn_smem);

    // 1) QKV projection
    sgemm_kernel<<<dim3(QKVD / 128, SEQ / 128), 256>>>(hidden, Wqkv, qkv_ptr, SEQ, QKVD, HIDDEN);
    // 2) RoPE (q + k heads, in place)
    rope_kernel<<<(SEQ * 40 * 32) / 256, 256>>>(positions);
    // 3) Causal GQA flash attention
    attn_kernel<<<dim3(SEQ / 64, NH), 256, attn_smem>>>();
    // 4) Output projection
    sgemm_kernel<<<dim3(HIDDEN / 128, SEQ / 128), 256>>>(attn_ptr, Wo, out, SEQ, HIDDEN, HIDDEN);
}

// round 5
// speedup vs baseline: 1.3657x; 1.3657x over previous
#include <cuda_runtime.h>
#include <cuda_bf16.h>
#include <cstdint>
#include <math.h>

#define SEQ    2048
#define HIDDEN 4096
#define NH     32
#define HD     128
#define NKV    8
#define QKVD   6144
#define KOFF   4096
#define VOFF   5120
#define KBIG   12288   // 3 * 4096 (split-precision K extension)
#define BK     64
#define NIT    192     // KBIG / BK
#define STAGES 4
#define ROWB   144     // 128B data + 16B pad (conflict-free ldmatrix)
#define STAGE_BYTES (128 * ROWB * 2)   // A tile + B tile = 36864
#define B_OFF  (128 * ROWB)

// ---------------- scratch (__device__ globals; no allocs allowed) ----------
__device__ float         g_qkv [SEQ * QKVD];
__device__ float         g_attn[SEQ * HIDDEN];
__device__ __nv_bfloat16 g_Ahl [SEQ * KBIG];
__device__ __nv_bfloat16 g_A2hl[SEQ * KBIG];
__device__ __nv_bfloat16 g_Bqkv[QKVD * KBIG];
__device__ __nv_bfloat16 g_Bo  [HIDDEN * KBIG];

__device__ __forceinline__ uint32_t smem_u32(const void* p) {
    uint32_t a;
    asm("{ .reg .u64 t; cvta.to.shared.u64 t, %1; cvt.u32.u64 %0, t; }" : "=r"(a) : "l"(p));
    return a;
}
#define CP_ASYNC16(dst, src) \
    asm volatile("cp.async.cg.shared.global [%0], [%1], 16;" :: "r"(dst), "l"(src) : "memory")

__device__ __forceinline__ void ldsm_x4(uint32_t* r, uint32_t addr) {
    asm volatile("ldmatrix.sync.aligned.m8n8.x4.shared.b16 {%0,%1,%2,%3}, [%4];"
                 : "=r"(r[0]), "=r"(r[1]), "=r"(r[2]), "=r"(r[3]) : "r"(addr));
}
__device__ __forceinline__ void mma16816(float* d, const uint32_t* a, const uint32_t* b) {
    asm volatile(
        "mma.sync.aligned.m16n8k16.row.col.f32.bf16.bf16.f32 "
        "{%0,%1,%2,%3}, {%4,%5,%6,%7}, {%8,%9}, {%0,%1,%2,%3};"
        : "+f"(d[0]), "+f"(d[1]), "+f"(d[2]), "+f"(d[3])
        : "r"(a[0]), "r"(a[1]), "r"(a[2]), "r"(a[3]), "r"(b[0]), "r"(b[1]));
}

// ---------------------------------------------------------------------------
// bf16 tensor-core GEMM via mma.sync: C[M,N] = A[M,KBIG] @ Bt[N,KBIG]^T
// BM=BN=128, BK=64, 256 threads (8 warps, 2x4), 4-stage cp.async pipeline.
// ---------------------------------------------------------------------------
__global__ __launch_bounds__(256, 1) void gemm_mma_kernel(
    const __nv_bfloat16* __restrict__ A,
    const __nv_bfloat16* __restrict__ Bt,
    float* __restrict__ C, int N)
{
    extern __shared__ char smem[];
    const uint32_t sb = smem_u32(smem);
    const int tid  = threadIdx.x;
    const int lane = tid & 31, warp = tid >> 5;
    const int wm = warp >> 2, wn = warp & 3;      // 2 x 4 warp grid
    const int mbase = blockIdx.y * 128;
    const int nbase = blockIdx.x * 128;

    const __nv_bfloat16* Arow = A  + (size_t)mbase * KBIG;
    const __nv_bfloat16* Brow = Bt + (size_t)nbase * KBIG;

    // per-thread cp.async mapping: 1024 A chunks + 1024 B chunks of 16B
    const int c_row = tid >> 1;            // 0..127
    const int c_ch0 = (tid & 1) * 4;       // 0 or 4 (4 chunks each)

    auto load_stage = [&](int itL, int stL) {
        const int kb = itL * BK;
        const uint32_t base = sb + stL * STAGE_BYTES;
        const char* asrc = (const char*)(Arow + (size_t)c_row * KBIG + kb);
        const char* bsrc = (const char*)(Brow + (size_t)c_row * KBIG + kb);
#pragma unroll
        for (int c = 0; c < 4; c++) {
            int ch = c_ch0 + c;
            CP_ASYNC16(base + c_row * ROWB + ch * 16,         asrc + ch * 16);
            CP_ASYNC16(base + B_OFF + c_row * ROWB + ch * 16, bsrc + ch * 16);
        }
    };

    float acc[4][4][4];
#pragma unroll
    for (int i = 0; i < 4; i++)
#pragma unroll
        for (int j = 0; j < 4; j++)
#pragma unroll
            for (int r = 0; r < 4; r++) acc[i][j][r] = 0.f;

#pragma unroll
    for (int s = 0; s < STAGES; s++) {
        load_stage(s, s);
        asm volatile("cp.async.commit_group;" ::: "memory");
    }

    // ldmatrix address components (constant per thread)
    const uint32_t a_row = wm * 64 + (lane & 15);
    const uint32_t a_kc  = (lane >> 4);               // +0/+1 chunk
    const uint32_t b_row0 = wn * 32 + (lane & 7);
    const uint32_t b_half = (lane >> 4) & 1;          // j vs j+1 tile
    const uint32_t b_kc   = (lane >> 3) & 1;          // k chunk parity

    for (int it = 0; it < NIT; it++) {
        const int st = it & 3;
        if      (it < NIT - 3) asm volatile("cp.async.wait_group 3;" ::: "memory");
        else if (it == NIT - 3) asm volatile("cp.async.wait_group 2;" ::: "memory");
        else if (it == NIT - 2) asm volatile("cp.async.wait_group 1;" ::: "memory");
        else                    asm volatile("cp.async.wait_group 0;" ::: "memory");
        __syncthreads();

        const uint32_t abase = sb + st * STAGE_BYTES;
        const uint32_t bbase = abase + B_OFF;

#pragma unroll
        for (int s = 0; s < 4; s++) {                 // 4 k16-steps per BK=64
            uint32_t af[4][4];
#pragma unroll
            for (int i = 0; i < 4; i++)
                ldsm_x4(af[i], abase + (a_row + i * 16) * ROWB + (s * 2 + a_kc) * 16);
            uint32_t bf[4][2];
#pragma unroll
            for (int jj = 0; jj < 2; jj++) {          // loads n-tiles (2jj, 2jj+1)
                uint32_t r[4];
                uint32_t brow = b_row0 + (2 * jj + b_half) * 8;
                ldsm_x4(r, bbase + brow * ROWB + (s * 2 + b_kc) * 16);
                bf[2 * jj][0] = r[0]; bf[2 * jj][1] = r[1];
                bf[2 * jj + 1][0] = r[2]; bf[2 * jj + 1][1] = r[3];
            }
#pragma unroll
            for (int i = 0; i < 4; i++)
#pragma unroll
                for (int j = 0; j < 4; j++)
                    mma16816(acc[i][j], af[i], bf[j]);
        }
        __syncthreads();

        if (it + STAGES < NIT) {
            load_stage(it + STAGES, st);
            asm volatile("cp.async.commit_group;" ::: "memory");
        }
    }

    // epilogue: direct fp32 stores (float2 per fragment half)
    const int g = lane >> 2, t = lane & 3;
#pragma unroll
    for (int i = 0; i < 4; i++) {
#pragma unroll
        for (int j = 0; j < 4; j++) {
            int row = mbase + wm * 64 + i * 16 + g;
            int col = nbase + wn * 32 + j * 8 + 2 * t;
            *(float2*)&C[(size_t)row * N + col] =
                make_float2(acc[i][j][0], acc[i][j][1]);
            *(float2*)&C[(size_t)(row + 8) * N + col] =
                make_float2(acc[i][j][2], acc[i][j][3]);
        }
    }
}

// ---------------------------------------------------------------------------
// fp32 -> bf16 hi/lo split, row blocks [hi, lo, hi]. X [M,4096] -> Y [M,12288]
// ---------------------------------------------------------------------------
__global__ __launch_bounds__(256) void split3_kernel(
    const float* __restrict__ X, __nv_bfloat16* __restrict__ Y, int total)
{
    int idx = blockIdx.x * blockDim.x + threadIdx.x;
    if (idx >= total) return;
    int k = idx & 4095;
    int s = idx >> 12;
    float x = X[idx];
    __nv_bfloat16 h = __float2bfloat16(x);
    __nv_bfloat16 l = __float2bfloat16(x - __bfloat162float(h));
    size_t base = (size_t)s * KBIG + k;
    Y[base] = h; Y[base + 4096] = l; Y[base + 8192] = h;
}

// ---------------------------------------------------------------------------
// W [4096, N] -> Bt [N, 12288], blocks [hi, hi, lo], tiled transpose.
// ---------------------------------------------------------------------------
__global__ __launch_bounds__(1024) void tsplit_kernel(
    const float* __restrict__ W, __nv_bfloat16* __restrict__ Bt, int N)
{
    __shared__ float t[32][33];
    int n0 = blockIdx.x * 32, k0 = blockIdx.y * 32;
    t[threadIdx.y][threadIdx.x] = W[(size_t)(k0 + threadIdx.y) * N + n0 + threadIdx.x];
    __syncthreads();
    float x = t[threadIdx.x][threadIdx.y];
    int n = n0 + threadIdx.y, k = k0 + threadIdx.x;
    __nv_bfloat16 h = __float2bfloat16(x);
    __nv_bfloat16 l = __float2bfloat16(x - __bfloat162float(h));
    size_t base = (size_t)n * KBIG + k;
    Bt[base] = h; Bt[base + 4096] = h; Bt[base + 8192] = l;
}

// ---------------------------------------------------------------------------
// RoPE. positions may be int32 or int64 words (layout sniffed).
// ---------------------------------------------------------------------------
__global__ __launch_bounds__(256) void rope_kernel(const int* __restrict__ pos32)
{
    int idx = blockIdx.x * blockDim.x + threadIdx.x;
    if (idx >= SEQ * 40 * 32) return;
    int j = idx & 31;
    int t = idx >> 5;
    int h = t % 40;
    int s = t / 40;
    bool is64 = (pos32[1] == 0);
    int posi = is64 ? pos32[2 * s] : pos32[s];
    float inv_freq = 1.0f / powf(10000.0f, (float)j * (1.0f / 32.0f));
    float f = (float)posi * inv_freq;
    float cs, sn;
    sincosf(f, &sn, &cs);
    int base = s * QKVD + ((h < 32) ? h * HD : KOFF + (h - 32) * HD);
    float x1 = g_qkv[base + j];
    float x2 = g_qkv[base + 32 + j];
    g_qkv[base + j]      = x1 * cs - x2 * sn;
    g_qkv[base + 32 + j] = x2 * cs + x1 * sn;
}

// ---------------------------------------------------------------------------
// Flash attention (unchanged, passing in R2).
// ---------------------------------------------------------------------------
__global__ __launch_bounds__(256) void attn_kernel()
{
    extern __shared__ float4 smem4[];
    float4* qs4 = smem4;
    float4* kt4 = qs4 + 64 * 32;
    float4* vs4 = kt4 + 32 * 33;

    const int tid  = threadIdx.x;
    const int lane = tid & 31;
    const int warp = tid >> 5;
    const int qt   = gridDim.x - 1 - blockIdx.x;
    const int h    = blockIdx.y;
    const int kvh  = h >> 2;
    const int qbase = qt * 64;

    for (int i = tid; i < 64 * 32; i += 256) {
        int row = i >> 5, d4 = i & 31;
        qs4[i] = *(const float4*)&g_qkv[(qbase + row) * QKVD + h * HD + d4 * 4];
    }
    __syncthreads();

    float m[8], l[8];
    float4 O[8];
#pragma unroll
    for (int r = 0; r < 8; r++) {
        m[r] = -INFINITY; l[r] = 0.f;
        O[r] = make_float4(0.f, 0.f, 0.f, 0.f);
    }

    const float scale = 0.088388347648318447f;
    const int ntiles = (qbase + 63) / 32 + 1;

    for (int t = 0; t < ntiles; t++) {
        const int kb = t * 32;
        for (int i = tid; i < 32 * 32; i += 256) {
            int key = i >> 5, d4 = i & 31;
            const float* kp = &g_qkv[(kb + key) * QKVD + KOFF + kvh * HD + d4 * 4];
            const float* vp = &g_qkv[(kb + key) * QKVD + VOFF + kvh * HD + d4 * 4];
            kt4[d4 * 33 + key] = *(const float4*)kp;
            vs4[key * 32 + d4] = *(const float4*)vp;
        }
        __syncthreads();

        float s[8];
#pragma unroll
        for (int r = 0; r < 8; r++) s[r] = 0.f;
#pragma unroll 4
        for (int d4 = 0; d4 < 32; d4++) {
            float4 kk = kt4[d4 * 33 + lane];
#pragma unroll
            for (int r = 0; r < 8; r++) {
                float4 q = qs4[(warp * 8 + r) * 32 + d4];
                s[r] += q.x * kk.x + q.y * kk.y + q.z * kk.z + q.w * kk.w;
            }
        }

        const int kg = kb + lane;
        float p[8];
#pragma unroll
        for (int r = 0; r < 8; r++) {
            int qg = qbase + warp * 8 + r;
            float sv = (kg <= qg) ? s[r] * scale : -INFINITY;
            float mt = sv;
#pragma unroll
            for (int o = 16; o; o >>= 1)
                mt = fmaxf(mt, __shfl_xor_sync(0xffffffffu, mt, o));
            float mn = fmaxf(m[r], mt);
            float pv = expf(sv - mn);
            float ls = pv;
#pragma unroll
            for (int o = 16; o; o >>= 1)
                ls += __shfl_xor_sync(0xffffffffu, ls, o);
            float alpha = expf(m[r] - mn);
            l[r] = l[r] * alpha + ls;
            m[r] = mn;
            O[r].x *= alpha; O[r].y *= alpha; O[r].z *= alpha; O[r].w *= alpha;
            p[r] = pv;
        }

#pragma unroll 4
        for (int k = 0; k < 32; k++) {
            float4 v = vs4[k * 32 + lane];
#pragma unroll
            for (int r = 0; r < 8; r++) {
                float pk = __shfl_sync(0xffffffffu, p[r], k);
                O[r].x += pk * v.x; O[r].y += pk * v.y;
                O[r].z += pk * v.z; O[r].w += pk * v.w;
            }
        }
        __syncthreads();
    }

#pragma unroll
    for (int r = 0; r < 8; r++) {
        int sg = qbase + warp * 8 + r;
        float inv = 1.0f / l[r];
        float4 o = make_float4(O[r].x * inv, O[r].y * inv, O[r].z * inv, O[r].w * inv);
        *(float4*)&g_attn[sg * HIDDEN + h * HD + lane * 4] = o;
    }
}

// ---------------------------------------------------------------------------
extern "C" void kernel_launch(void* const* d_in, const int* in_sizes, int n_in,
                              void* d_out, int out_size)
{
    const float* hidden    = (const float*)d_in[0];
    const float* Wqkv      = (const float*)d_in[1];
    const float* Wo        = (const float*)d_in[2];
    const int*   positions = (const int*)d_in[3];
    float*       out       = (float*)d_out;

    float *qkv_ptr, *attn_ptr;
    __nv_bfloat16 *Ahl, *A2hl, *Bqkv, *Bo;
    cudaGetSymbolAddress((void**)&qkv_ptr,  g_qkv);
    cudaGetSymbolAddress((void**)&attn_ptr, g_attn);
    cudaGetSymbolAddress((void**)&Ahl,  g_Ahl);
    cudaGetSymbolAddress((void**)&A2hl, g_A2hl);
    cudaGetSymbolAddress((void**)&Bqkv, g_Bqkv);
    cudaGetSymbolAddress((void**)&Bo,   g_Bo);

    const int gemm_smem = STAGES * STAGE_BYTES;   // 147456
    cudaFuncSetAttribute(gemm_mma_kernel, cudaFuncAttributeMaxDynamicSharedMemorySize, gemm_smem);
    const int attn_smem = (64 * 32 + 32 * 33 + 32 * 32) * 16;
    cudaFuncSetAttribute(attn_kernel, cudaFuncAttributeMaxDynamicSharedMemorySize, attn_smem);

    // operand conversion (split precision + B transpose)
    split3_kernel<<<(SEQ * HIDDEN) / 256, 256>>>(hidden, Ahl, SEQ * HIDDEN);
    tsplit_kernel<<<dim3(QKVD / 32, HIDDEN / 32), dim3(32, 32)>>>(Wqkv, Bqkv, QKVD);
    tsplit_kernel<<<dim3(HIDDEN / 32, HIDDEN / 32), dim3(32, 32)>>>(Wo, Bo, HIDDEN);

    // 1) QKV projection (mma.sync bf16, split precision)
    gemm_mma_kernel<<<dim3(QKVD / 128, SEQ / 128), 256, gemm_smem>>>(Ahl, Bqkv, qkv_ptr, QKVD);
    // 2) RoPE
    rope_kernel<<<(SEQ * 40 * 32) / 256, 256>>>(positions);
    // 3) Causal GQA flash attention
    attn_kernel<<<dim3(SEQ / 64, NH), 256, attn_smem>>>();
    // 4) Output projection
    split3_kernel<<<(SEQ * HIDDEN) / 256, 256>>>(attn_ptr, A2hl, SEQ * HIDDEN);
    gemm_mma_kernel<<<dim3(HIDDEN / 128, SEQ / 128), 256, gemm_smem>>>(A2hl, Bo, out, HIDDEN);
}

// round 6
// speedup vs baseline: 1.5049x; 1.1020x over previous
#include <cuda_runtime.h>
#include <cuda_bf16.h>
#include <cstdint>
#include <math.h>

#define SEQ    2048
#define HIDDEN 4096
#define NH     32
#define HD     128
#define NKV    8
#define QKVD   6144
#define KOFF   4096
#define VOFF   5120
#define KBIG   12288   // 3 * 4096 (split-precision K extension)
#define BK     64
#define NIT    192     // KBIG / BK
#define STAGES 3
#define ROWB   144     // 128B data + 16B pad (conflict-free ldmatrix)
#define STAGE_BYTES (128 * ROWB * 2)   // A tile + B tile = 36864
#define B_OFF  (128 * ROWB)

// ---------------- scratch (__device__ globals; no allocs allowed) ----------
__device__ float         g_qkv [SEQ * QKVD];
__device__ float         g_attn[SEQ * HIDDEN];
__device__ __nv_bfloat16 g_Ahl [SEQ * KBIG];
__device__ __nv_bfloat16 g_A2hl[SEQ * KBIG];
__device__ __nv_bfloat16 g_Bqkv[QKVD * KBIG];
__device__ __nv_bfloat16 g_Bo  [HIDDEN * KBIG];

__device__ __forceinline__ uint32_t smem_u32(const void* p) {
    uint32_t a;
    asm("{ .reg .u64 t; cvta.to.shared.u64 t, %1; cvt.u32.u64 %0, t; }" : "=r"(a) : "l"(p));
    return a;
}
#define CP_ASYNC16(dst, src) \
    asm volatile("cp.async.cg.shared.global [%0], [%1], 16;" :: "r"(dst), "l"(src) : "memory")

__device__ __forceinline__ void ldsm_x4(uint32_t* r, uint32_t addr) {
    asm volatile("ldmatrix.sync.aligned.m8n8.x4.shared.b16 {%0,%1,%2,%3}, [%4];"
                 : "=r"(r[0]), "=r"(r[1]), "=r"(r[2]), "=r"(r[3]) : "r"(addr));
}
__device__ __forceinline__ void mma16816(float* d, const uint32_t* a, const uint32_t* b) {
    asm volatile(
        "mma.sync.aligned.m16n8k16.row.col.f32.bf16.bf16.f32 "
        "{%0,%1,%2,%3}, {%4,%5,%6,%7}, {%8,%9}, {%0,%1,%2,%3};"
        : "+f"(d[0]), "+f"(d[1]), "+f"(d[2]), "+f"(d[3])
        : "r"(a[0]), "r"(a[1]), "r"(a[2]), "r"(a[3]), "r"(b[0]), "r"(b[1]));
}

// ---------------------------------------------------------------------------
// bf16 tensor-core GEMM via mma.sync: C[M,N] = A[M,KBIG] @ Bt[N,KBIG]^T
// BM=BN=128, BK=64, 256 threads (8 warps, 2x4), 3-stage cp.async pipeline,
// 2 CTAs per SM (smem 110.6KB, <=128 regs).
// ---------------------------------------------------------------------------
__global__ __launch_bounds__(256, 2) void gemm_mma_kernel(
    const __nv_bfloat16* __restrict__ A,
    const __nv_bfloat16* __restrict__ Bt,
    float* __restrict__ C, int N)
{
    extern __shared__ char smem[];
    const uint32_t sb = smem_u32(smem);
    const int tid  = threadIdx.x;
    const int lane = tid & 31, warp = tid >> 5;
    const int wm = warp >> 2, wn = warp & 3;      // 2 x 4 warp grid
    const int mbase = blockIdx.y * 128;
    const int nbase = blockIdx.x * 128;

    const __nv_bfloat16* Arow = A  + (size_t)mbase * KBIG;
    const __nv_bfloat16* Brow = Bt + (size_t)nbase * KBIG;

    // per-thread cp.async mapping: 1024 A chunks + 1024 B chunks of 16B
    const int c_row = tid >> 1;            // 0..127
    const int c_ch0 = (tid & 1) * 4;       // 0 or 4 (4 chunks each)

    auto load_stage = [&](int itL, int stL) {
        const int kb = itL * BK;
        const uint32_t base = sb + stL * STAGE_BYTES;
        const char* asrc = (const char*)(Arow + (size_t)c_row * KBIG + kb);
        const char* bsrc = (const char*)(Brow + (size_t)c_row * KBIG + kb);
#pragma unroll
        for (int c = 0; c < 4; c++) {
            int ch = c_ch0 + c;
            CP_ASYNC16(base + c_row * ROWB + ch * 16,         asrc + ch * 16);
            CP_ASYNC16(base + B_OFF + c_row * ROWB + ch * 16, bsrc + ch * 16);
        }
    };

    float acc[4][4][4];
#pragma unroll
    for (int i = 0; i < 4; i++)
#pragma unroll
        for (int j = 0; j < 4; j++)
#pragma unroll
            for (int r = 0; r < 4; r++) acc[i][j][r] = 0.f;

#pragma unroll
    for (int s = 0; s < STAGES; s++) {
        load_stage(s, s);
        asm volatile("cp.async.commit_group;" ::: "memory");
    }

    // ldmatrix address components (constant per thread)
    const uint32_t a_row = wm * 64 + (lane & 15);
    const uint32_t a_kc  = (lane >> 4);               // +0/+1 chunk
    const uint32_t b_row0 = wn * 32 + (lane & 7);
    const uint32_t b_half = (lane >> 4) & 1;          // j vs j+1 tile
    const uint32_t b_kc   = (lane >> 3) & 1;          // k chunk parity

    for (int it = 0; it < NIT; it++) {
        const int st = it % 3;
        if      (it < NIT - 2)  asm volatile("cp.async.wait_group 2;" ::: "memory");
        else if (it == NIT - 2) asm volatile("cp.async.wait_group 1;" ::: "memory");
        else                    asm volatile("cp.async.wait_group 0;" ::: "memory");
        __syncthreads();

        const uint32_t abase = sb + st * STAGE_BYTES;
        const uint32_t bbase = abase + B_OFF;

#pragma unroll
        for (int s = 0; s < 4; s++) {                 // 4 k16-steps per BK=64
            uint32_t af[4][4];
#pragma unroll
            for (int i = 0; i < 4; i++)
                ldsm_x4(af[i], abase + (a_row + i * 16) * ROWB + (s * 2 + a_kc) * 16);
            uint32_t bf[4][2];
#pragma unroll
            for (int jj = 0; jj < 2; jj++) {          // loads n-tiles (2jj, 2jj+1)
                uint32_t r[4];
                uint32_t brow = b_row0 + (2 * jj + b_half) * 8;
                ldsm_x4(r, bbase + brow * ROWB + (s * 2 + b_kc) * 16);
                bf[2 * jj][0] = r[0]; bf[2 * jj][1] = r[1];
                bf[2 * jj + 1][0] = r[2]; bf[2 * jj + 1][1] = r[3];
            }
#pragma unroll
            for (int i = 0; i < 4; i++)
#pragma unroll
                for (int j = 0; j < 4; j++)
                    mma16816(acc[i][j], af[i], bf[j]);
        }
        __syncthreads();

        if (it + STAGES < NIT) {
            load_stage(it + STAGES, st);
            asm volatile("cp.async.commit_group;" ::: "memory");
        }
    }

    // epilogue: direct fp32 stores (float2 per fragment half)
    const int g = lane >> 2, t = lane & 3;
#pragma unroll
    for (int i = 0; i < 4; i++) {
#pragma unroll
        for (int j = 0; j < 4; j++) {
            int row = mbase + wm * 64 + i * 16 + g;
            int col = nbase + wn * 32 + j * 8 + 2 * t;
            *(float2*)&C[(size_t)row * N + col] =
                make_float2(acc[i][j][0], acc[i][j][1]);
            *(float2*)&C[(size_t)(row + 8) * N + col] =
                make_float2(acc[i][j][2], acc[i][j][3]);
        }
    }
}

// ---------------------------------------------------------------------------
// fp32 -> bf16 hi/lo split, row blocks [hi, lo, hi]. X [M,4096] -> Y [M,12288]
// ---------------------------------------------------------------------------
__global__ __launch_bounds__(256) void split3_kernel(
    const float* __restrict__ X, __nv_bfloat16* __restrict__ Y, int total)
{
    int idx = blockIdx.x * blockDim.x + threadIdx.x;
    if (idx >= total) return;
    int k = idx & 4095;
    int s = idx >> 12;
    float x = X[idx];
    __nv_bfloat16 h = __float2bfloat16(x);
    __nv_bfloat16 l = __float2bfloat16(x - __bfloat162float(h));
    size_t base = (size_t)s * KBIG + k;
    Y[base] = h; Y[base + 4096] = l; Y[base + 8192] = h;
}

// ---------------------------------------------------------------------------
// W [4096, N] -> Bt [N, 12288], blocks [hi, hi, lo], tiled transpose.
// ---------------------------------------------------------------------------
__global__ __launch_bounds__(1024) void tsplit_kernel(
    const float* __restrict__ W, __nv_bfloat16* __restrict__ Bt, int N)
{
    __shared__ float t[32][33];
    int n0 = blockIdx.x * 32, k0 = blockIdx.y * 32;
    t[threadIdx.y][threadIdx.x] = W[(size_t)(k0 + threadIdx.y) * N + n0 + threadIdx.x];
    __syncthreads();
    float x = t[threadIdx.x][threadIdx.y];
    int n = n0 + threadIdx.y, k = k0 + threadIdx.x;
    __nv_bfloat16 h = __float2bfloat16(x);
    __nv_bfloat16 l = __float2bfloat16(x - __bfloat162float(h));
    size_t base = (size_t)n * KBIG + k;
    Bt[base] = h; Bt[base + 4096] = h; Bt[base + 8192] = l;
}

// ---------------------------------------------------------------------------
// RoPE. positions may be int32 or int64 words (layout sniffed).
// ---------------------------------------------------------------------------
__global__ __launch_bounds__(256) void rope_kernel(const int* __restrict__ pos32)
{
    int idx = blockIdx.x * blockDim.x + threadIdx.x;
    if (idx >= SEQ * 40 * 32) return;
    int j = idx & 31;
    int t = idx >> 5;
    int h = t % 40;
    int s = t / 40;
    bool is64 = (pos32[1] == 0);
    int posi = is64 ? pos32[2 * s] : pos32[s];
    float inv_freq = 1.0f / powf(10000.0f, (float)j * (1.0f / 32.0f));
    float f = (float)posi * inv_freq;
    float cs, sn;
    sincosf(f, &sn, &cs);
    int base = s * QKVD + ((h < 32) ? h * HD : KOFF + (h - 32) * HD);
    float x1 = g_qkv[base + j];
    float x2 = g_qkv[base + 32 + j];
    g_qkv[base + j]      = x1 * cs - x2 * sn;
    g_qkv[base + 32 + j] = x2 * cs + x1 * sn;
}

// ---------------------------------------------------------------------------
// Flash attention (unchanged, passing).
// ---------------------------------------------------------------------------
__global__ __launch_bounds__(256) void attn_kernel()
{
    extern __shared__ float4 smem4[];
    float4* qs4 = smem4;
    float4* kt4 = qs4 + 64 * 32;
    float4* vs4 = kt4 + 32 * 33;

    const int tid  = threadIdx.x;
    const int lane = tid & 31;
    const int warp = tid >> 5;
    const int qt   = gridDim.x - 1 - blockIdx.x;
    const int h    = blockIdx.y;
    const int kvh  = h >> 2;
    const int qbase = qt * 64;

    for (int i = tid; i < 64 * 32; i += 256) {
        int row = i >> 5, d4 = i & 31;
        qs4[i] = *(const float4*)&g_qkv[(qbase + row) * QKVD + h * HD + d4 * 4];
    }
    __syncthreads();

    float m[8], l[8];
    float4 O[8];
#pragma unroll
    for (int r = 0; r < 8; r++) {
        m[r] = -INFINITY; l[r] = 0.f;
        O[r] = make_float4(0.f, 0.f, 0.f, 0.f);
    }

    const float scale = 0.088388347648318447f;
    const int ntiles = (qbase + 63) / 32 + 1;

    for (int t = 0; t < ntiles; t++) {
        const int kb = t * 32;
        for (int i = tid; i < 32 * 32; i += 256) {
            int key = i >> 5, d4 = i & 31;
            const float* kp = &g_qkv[(kb + key) * QKVD + KOFF + kvh * HD + d4 * 4];
            const float* vp = &g_qkv[(kb + key) * QKVD + VOFF + kvh * HD + d4 * 4];
            kt4[d4 * 33 + key] = *(const float4*)kp;
            vs4[key * 32 + d4] = *(const float4*)vp;
        }
        __syncthreads();

        float s[8];
#pragma unroll
        for (int r = 0; r < 8; r++) s[r] = 0.f;
#pragma unroll 4
        for (int d4 = 0; d4 < 32; d4++) {
            float4 kk = kt4[d4 * 33 + lane];
#pragma unroll
            for (int r = 0; r < 8; r++) {
                float4 q = qs4[(warp * 8 + r) * 32 + d4];
                s[r] += q.x * kk.x + q.y * kk.y + q.z * kk.z + q.w * kk.w;
            }
        }

        const int kg = kb + lane;
        float p[8];
#pragma unroll
        for (int r = 0; r < 8; r++) {
            int qg = qbase + warp * 8 + r;
            float sv = (kg <= qg) ? s[r] * scale : -INFINITY;
            float mt = sv;
#pragma unroll
            for (int o = 16; o; o >>= 1)
                mt = fmaxf(mt, __shfl_xor_sync(0xffffffffu, mt, o));
            float mn = fmaxf(m[r], mt);
            float pv = expf(sv - mn);
            float ls = pv;
#pragma unroll
            for (int o = 16; o; o >>= 1)
                ls += __shfl_xor_sync(0xffffffffu, ls, o);
            float alpha = expf(m[r] - mn);
            l[r] = l[r] * alpha + ls;
            m[r] = mn;
            O[r].x *= alpha; O[r].y *= alpha; O[r].z *= alpha; O[r].w *= alpha;
            p[r] = pv;
        }

#pragma unroll 4
        for (int k = 0; k < 32; k++) {
            float4 v = vs4[k * 32 + lane];
#pragma unroll
            for (int r = 0; r < 8; r++) {
                float pk = __shfl_sync(0xffffffffu, p[r], k);
                O[r].x += pk * v.x; O[r].y += pk * v.y;
                O[r].z += pk * v.z; O[r].w += pk * v.w;
            }
        }
        __syncthreads();
    }

#pragma unroll
    for (int r = 0; r < 8; r++) {
        int sg = qbase + warp * 8 + r;
        float inv = 1.0f / l[r];
        float4 o = make_float4(O[r].x * inv, O[r].y * inv, O[r].z * inv, O[r].w * inv);
        *(float4*)&g_attn[sg * HIDDEN + h * HD + lane * 4] = o;
    }
}

// ---------------------------------------------------------------------------
extern "C" void kernel_launch(void* const* d_in, const int* in_sizes, int n_in,
                              void* d_out, int out_size)
{
    const float* hidden    = (const float*)d_in[0];
    const float* Wqkv      = (const float*)d_in[1];
    const float* Wo        = (const float*)d_in[2];
    const int*   positions = (const int*)d_in[3];
    float*       out       = (float*)d_out;

    float *qkv_ptr, *attn_ptr;
    __nv_bfloat16 *Ahl, *A2hl, *Bqkv, *Bo;
    cudaGetSymbolAddress((void**)&qkv_ptr,  g_qkv);
    cudaGetSymbolAddress((void**)&attn_ptr, g_attn);
    cudaGetSymbolAddress((void**)&Ahl,  g_Ahl);
    cudaGetSymbolAddress((void**)&A2hl, g_A2hl);
    cudaGetSymbolAddress((void**)&Bqkv, g_Bqkv);
    cudaGetSymbolAddress((void**)&Bo,   g_Bo);

    const int gemm_smem = STAGES * STAGE_BYTES;   // 110592 -> 2 CTAs/SM
    cudaFuncSetAttribute(gemm_mma_kernel, cudaFuncAttributeMaxDynamicSharedMemorySize, gemm_smem);
    const int attn_smem = (64 * 32 + 32 * 33 + 32 * 32) * 16;
    cudaFuncSetAttribute(attn_kernel, cudaFuncAttributeMaxDynamicSharedMemorySize, attn_smem);

    // operand conversion (split precision + B transpose)
    split3_kernel<<<(SEQ * HIDDEN) / 256, 256>>>(hidden, Ahl, SEQ * HIDDEN);
    tsplit_kernel<<<dim3(QKVD / 32, HIDDEN / 32), dim3(32, 32)>>>(Wqkv, Bqkv, QKVD);
    tsplit_kernel<<<dim3(HIDDEN / 32, HIDDEN / 32), dim3(32, 32)>>>(Wo, Bo, HIDDEN);

    // 1) QKV projection (mma.sync bf16, split precision)
    gemm_mma_kernel<<<dim3(QKVD / 128, SEQ / 128), 256, gemm_smem>>>(Ahl, Bqkv, qkv_ptr, QKVD);
    // 2) RoPE
    rope_kernel<<<(SEQ * 40 * 32) / 256, 256>>>(positions);
    // 3) Causal GQA flash attention
    attn_kernel<<<dim3(SEQ / 64, NH), 256, attn_smem>>>();
    // 4) Output projection
    split3_kernel<<<(SEQ * HIDDEN) / 256, 256>>>(attn_ptr, A2hl, SEQ * HIDDEN);
    gemm_mma_kernel<<<dim3(HIDDEN / 128, SEQ / 128), 256, gemm_smem>>>(A2hl, Bo, out, HIDDEN);
}

// round 7
// speedup vs baseline: 1.8732x; 1.2447x over previous
#include <cuda_runtime.h>
#include <cuda_fp16.h>
#include <cstdint>
#include <math.h>

#define SEQ    2048
#define HIDDEN 4096
#define NH     32
#define HD     128
#define NKV    8
#define QKVD   6144
#define KOFF   4096
#define VOFF   5120
#define KA     8192    // A split-precision width: [Ah | Al]
#define KB     4096    // B width: fp16 hi only (reused for both K halves)
#define BK     64
#define NIT    128     // KA / BK
#define STAGES 3
#define ROWB   144     // 128B data + 16B pad (conflict-free ldmatrix)
#define STAGE_BYTES (128 * ROWB * 2)   // A tile + B tile = 36864
#define B_OFF  (128 * ROWB)

// ---------------- scratch (__device__ globals; no allocs allowed) ----------
__device__ float  g_qkv [SEQ * QKVD];
__device__ float  g_attn[SEQ * HIDDEN];
__device__ __half g_Ahl [SEQ * KA];        // hidden split  [2048, 8192]
__device__ __half g_A2hl[SEQ * KA];        // attn split    [2048, 8192]
__device__ __half g_Bqkv[QKVD * KB];       // Wqkv^T hi     [6144, 4096]
__device__ __half g_Bo  [HIDDEN * KB];     // Wo^T   hi     [4096, 4096]

__device__ __forceinline__ uint32_t smem_u32(const void* p) {
    uint32_t a;
    asm("{ .reg .u64 t; cvta.to.shared.u64 t, %1; cvt.u32.u64 %0, t; }" : "=r"(a) : "l"(p));
    return a;
}
#define CP_ASYNC16(dst, src) \
    asm volatile("cp.async.cg.shared.global [%0], [%1], 16;" :: "r"(dst), "l"(src) : "memory")

__device__ __forceinline__ void ldsm_x4(uint32_t* r, uint32_t addr) {
    asm volatile("ldmatrix.sync.aligned.m8n8.x4.shared.b16 {%0,%1,%2,%3}, [%4];"
                 : "=r"(r[0]), "=r"(r[1]), "=r"(r[2]), "=r"(r[3]) : "r"(addr));
}
__device__ __forceinline__ void mma16816(float* d, const uint32_t* a, const uint32_t* b) {
    asm volatile(
        "mma.sync.aligned.m16n8k16.row.col.f32.f16.f16.f32 "
        "{%0,%1,%2,%3}, {%4,%5,%6,%7}, {%8,%9}, {%0,%1,%2,%3};"
        : "+f"(d[0]), "+f"(d[1]), "+f"(d[2]), "+f"(d[3])
        : "r"(a[0]), "r"(a[1]), "r"(a[2]), "r"(a[3]), "r"(b[0]), "r"(b[1]));
}

// ---------------------------------------------------------------------------
// fp16 tensor-core GEMM via mma.sync: C[M,N] = A[M,KA] @ Bt[N,KB]^T where the
// A K-axis is [Ah | Al] and B's 4096 columns are consumed twice (kb & 4095).
// BM=BN=128, BK=64, 256 threads (8 warps, 2x4), 3-stage cp.async, 2 CTA/SM.
// ---------------------------------------------------------------------------
__global__ __launch_bounds__(256, 2) void gemm_mma_kernel(
    const __half* __restrict__ A,
    const __half* __restrict__ Bt,
    float* __restrict__ C, int N)
{
    extern __shared__ char smem[];
    const uint32_t sb = smem_u32(smem);
    const int tid  = threadIdx.x;
    const int lane = tid & 31, warp = tid >> 5;
    const int wm = warp >> 2, wn = warp & 3;      // 2 x 4 warp grid
    const int mbase = blockIdx.y * 128;
    const int nbase = blockIdx.x * 128;

    const __half* Arow = A  + (size_t)mbase * KA;
    const __half* Brow = Bt + (size_t)nbase * KB;

    // per-thread cp.async mapping: 1024 A chunks + 1024 B chunks of 16B
    const int c_row = tid >> 1;            // 0..127
    const int c_ch0 = (tid & 1) * 4;       // 0 or 4 (4 chunks each)

    auto load_stage = [&](int itL, int stL) {
        const int kbA = itL * BK;
        const int kbB = (itL * BK) & (KB - 1);
        const uint32_t base = sb + stL * STAGE_BYTES;
        const char* asrc = (const char*)(Arow + (size_t)c_row * KA + kbA);
        const char* bsrc = (const char*)(Brow + (size_t)c_row * KB + kbB);
#pragma unroll
        for (int c = 0; c < 4; c++) {
            int ch = c_ch0 + c;
            CP_ASYNC16(base + c_row * ROWB + ch * 16,         asrc + ch * 16);
            CP_ASYNC16(base + B_OFF + c_row * ROWB + ch * 16, bsrc + ch * 16);
        }
    };

    float acc[4][4][4];
#pragma unroll
    for (int i = 0; i < 4; i++)
#pragma unroll
        for (int j = 0; j < 4; j++)
#pragma unroll
            for (int r = 0; r < 4; r++) acc[i][j][r] = 0.f;

#pragma unroll
    for (int s = 0; s < STAGES; s++) {
        load_stage(s, s);
        asm volatile("cp.async.commit_group;" ::: "memory");
    }

    // ldmatrix address components (constant per thread)
    const uint32_t a_row = wm * 64 + (lane & 15);
    const uint32_t a_kc  = (lane >> 4);               // +0/+1 chunk
    const uint32_t b_row0 = wn * 32 + (lane & 7);
    const uint32_t b_half = (lane >> 4) & 1;          // j vs j+1 tile
    const uint32_t b_kc   = (lane >> 3) & 1;          // k chunk parity

    for (int it = 0; it < NIT; it++) {
        const int st = it % 3;
        if      (it < NIT - 2)  asm volatile("cp.async.wait_group 2;" ::: "memory");
        else if (it == NIT - 2) asm volatile("cp.async.wait_group 1;" ::: "memory");
        else                    asm volatile("cp.async.wait_group 0;" ::: "memory");
        __syncthreads();

        const uint32_t abase = sb + st * STAGE_BYTES;
        const uint32_t bbase = abase + B_OFF;

#pragma unroll
        for (int s = 0; s < 4; s++) {                 // 4 k16-steps per BK=64
            uint32_t af[4][4];
#pragma unroll
            for (int i = 0; i < 4; i++)
                ldsm_x4(af[i], abase + (a_row + i * 16) * ROWB + (s * 2 + a_kc) * 16);
            uint32_t bf[4][2];
#pragma unroll
            for (int jj = 0; jj < 2; jj++) {          // loads n-tiles (2jj, 2jj+1)
                uint32_t r[4];
                uint32_t brow = b_row0 + (2 * jj + b_half) * 8;
                ldsm_x4(r, bbase + brow * ROWB + (s * 2 + b_kc) * 16);
                bf[2 * jj][0] = r[0]; bf[2 * jj][1] = r[1];
                bf[2 * jj + 1][0] = r[2]; bf[2 * jj + 1][1] = r[3];
            }
#pragma unroll
            for (int i = 0; i < 4; i++)
#pragma unroll
                for (int j = 0; j < 4; j++)
                    mma16816(acc[i][j], af[i], bf[j]);
        }
        __syncthreads();

        if (it + STAGES < NIT) {
            load_stage(it + STAGES, st);
            asm volatile("cp.async.commit_group;" ::: "memory");
        }
    }

    // epilogue: direct fp32 stores (float2 per fragment half)
    const int g = lane >> 2, t = lane & 3;
#pragma unroll
    for (int i = 0; i < 4; i++) {
#pragma unroll
        for (int j = 0; j < 4; j++) {
            int row = mbase + wm * 64 + i * 16 + g;
            int col = nbase + wn * 32 + j * 8 + 2 * t;
            *(float2*)&C[(size_t)row * N + col] =
                make_float2(acc[i][j][0], acc[i][j][1]);
            *(float2*)&C[(size_t)(row + 8) * N + col] =
                make_float2(acc[i][j][2], acc[i][j][3]);
        }
    }
}

// ---------------------------------------------------------------------------
// fp32 -> fp16 hi/lo split: X [M,4096] -> Y [M,8192] blocks [hi | lo]
// ---------------------------------------------------------------------------
__global__ __launch_bounds__(256) void split2_kernel(
    const float* __restrict__ X, __half* __restrict__ Y, int total)
{
    int idx = blockIdx.x * blockDim.x + threadIdx.x;
    if (idx >= total) return;
    int k = idx & 4095;
    int s = idx >> 12;
    float x = X[idx];
    __half h = __float2half(x);
    __half l = __float2half(x - __half2float(h));
    size_t base = (size_t)s * KA + k;
    Y[base] = h; Y[base + 4096] = l;
}

// ---------------------------------------------------------------------------
// W [4096, N] -> Bt [N, 4096] fp16 hi, tiled transpose.
// ---------------------------------------------------------------------------
__global__ __launch_bounds__(1024) void tsplit_kernel(
    const float* __restrict__ W, __half* __restrict__ Bt, int N)
{
    __shared__ float t[32][33];
    int n0 = blockIdx.x * 32, k0 = blockIdx.y * 32;
    t[threadIdx.y][threadIdx.x] = W[(size_t)(k0 + threadIdx.y) * N + n0 + threadIdx.x];
    __syncthreads();
    float x = t[threadIdx.x][threadIdx.y];
    int n = n0 + threadIdx.y, k = k0 + threadIdx.x;
    Bt[(size_t)n * KB + k] = __float2half(x);
}

// ---------------------------------------------------------------------------
// RoPE. positions may be int32 or int64 words (layout sniffed).
// ---------------------------------------------------------------------------
__global__ __launch_bounds__(256) void rope_kernel(const int* __restrict__ pos32)
{
    int idx = blockIdx.x * blockDim.x + threadIdx.x;
    if (idx >= SEQ * 40 * 32) return;
    int j = idx & 31;
    int t = idx >> 5;
    int h = t % 40;
    int s = t / 40;
    bool is64 = (pos32[1] == 0);
    int posi = is64 ? pos32[2 * s] : pos32[s];
    float inv_freq = 1.0f / powf(10000.0f, (float)j * (1.0f / 32.0f));
    float f = (float)posi * inv_freq;
    float cs, sn;
    sincosf(f, &sn, &cs);
    int base = s * QKVD + ((h < 32) ? h * HD : KOFF + (h - 32) * HD);
    float x1 = g_qkv[base + j];
    float x2 = g_qkv[base + 32 + j];
    g_qkv[base + j]      = x1 * cs - x2 * sn;
    g_qkv[base + 32 + j] = x2 * cs + x1 * sn;
}

// ---------------------------------------------------------------------------
// Flash attention (unchanged, passing).
// ---------------------------------------------------------------------------
__global__ __launch_bounds__(256) void attn_kernel()
{
    extern __shared__ float4 smem4[];
    float4* qs4 = smem4;
    float4* kt4 = qs4 + 64 * 32;
    float4* vs4 = kt4 + 32 * 33;

    const int tid  = threadIdx.x;
    const int lane = tid & 31;
    const int warp = tid >> 5;
    const int qt   = gridDim.x - 1 - blockIdx.x;
    const int h    = blockIdx.y;
    const int kvh  = h >> 2;
    const int qbase = qt * 64;

    for (int i = tid; i < 64 * 32; i += 256) {
        int row = i >> 5, d4 = i & 31;
        qs4[i] = *(const float4*)&g_qkv[(qbase + row) * QKVD + h * HD + d4 * 4];
    }
    __syncthreads();

    float m[8], l[8];
    float4 O[8];
#pragma unroll
    for (int r = 0; r < 8; r++) {
        m[r] = -INFINITY; l[r] = 0.f;
        O[r] = make_float4(0.f, 0.f, 0.f, 0.f);
    }

    const float scale = 0.088388347648318447f;
    const int ntiles = (qbase + 63) / 32 + 1;

    for (int t = 0; t < ntiles; t++) {
        const int kb = t * 32;
        for (int i = tid; i < 32 * 32; i += 256) {
            int key = i >> 5, d4 = i & 31;
            const float* kp = &g_qkv[(kb + key) * QKVD + KOFF + kvh * HD + d4 * 4];
            const float* vp = &g_qkv[(kb + key) * QKVD + VOFF + kvh * HD + d4 * 4];
            kt4[d4 * 33 + key] = *(const float4*)kp;
            vs4[key * 32 + d4] = *(const float4*)vp;
        }
        __syncthreads();

        float s[8];
#pragma unroll
        for (int r = 0; r < 8; r++) s[r] = 0.f;
#pragma unroll 4
        for (int d4 = 0; d4 < 32; d4++) {
            float4 kk = kt4[d4 * 33 + lane];
#pragma unroll
            for (int r = 0; r < 8; r++) {
                float4 q = qs4[(warp * 8 + r) * 32 + d4];
                s[r] += q.x * kk.x + q.y * kk.y + q.z * kk.z + q.w * kk.w;
            }
        }

        const int kg = kb + lane;
        float p[8];
#pragma unroll
        for (int r = 0; r < 8; r++) {
            int qg = qbase + warp * 8 + r;
            float sv = (kg <= qg) ? s[r] * scale : -INFINITY;
            float mt = sv;
#pragma unroll
            for (int o = 16; o; o >>= 1)
                mt = fmaxf(mt, __shfl_xor_sync(0xffffffffu, mt, o));
            float mn = fmaxf(m[r], mt);
            float pv = expf(sv - mn);
            float ls = pv;
#pragma unroll
            for (int o = 16; o; o >>= 1)
                ls += __shfl_xor_sync(0xffffffffu, ls, o);
            float alpha = expf(m[r] - mn);
            l[r] = l[r] * alpha + ls;
            m[r] = mn;
            O[r].x *= alpha; O[r].y *= alpha; O[r].z *= alpha; O[r].w *= alpha;
            p[r] = pv;
        }

#pragma unroll 4
        for (int k = 0; k < 32; k++) {
            float4 v = vs4[k * 32 + lane];
#pragma unroll
            for (int r = 0; r < 8; r++) {
                float pk = __shfl_sync(0xffffffffu, p[r], k);
                O[r].x += pk * v.x; O[r].y += pk * v.y;
                O[r].z += pk * v.z; O[r].w += pk * v.w;
            }
        }
        __syncthreads();
    }

#pragma unroll
    for (int r = 0; r < 8; r++) {
        int sg = qbase + warp * 8 + r;
        float inv = 1.0f / l[r];
        float4 o = make_float4(O[r].x * inv, O[r].y * inv, O[r].z * inv, O[r].w * inv);
        *(float4*)&g_attn[sg * HIDDEN + h * HD + lane * 4] = o;
    }
}

// ---------------------------------------------------------------------------
extern "C" void kernel_launch(void* const* d_in, const int* in_sizes, int n_in,
                              void* d_out, int out_size)
{
    const float* hidden    = (const float*)d_in[0];
    const float* Wqkv      = (const float*)d_in[1];
    const float* Wo        = (const float*)d_in[2];
    const int*   positions = (const int*)d_in[3];
    float*       out       = (float*)d_out;

    float *qkv_ptr, *attn_ptr;
    __half *Ahl, *A2hl, *Bqkv, *Bo;
    cudaGetSymbolAddress((void**)&qkv_ptr,  g_qkv);
    cudaGetSymbolAddress((void**)&attn_ptr, g_attn);
    cudaGetSymbolAddress((void**)&Ahl,  g_Ahl);
    cudaGetSymbolAddress((void**)&A2hl, g_A2hl);
    cudaGetSymbolAddress((void**)&Bqkv, g_Bqkv);
    cudaGetSymbolAddress((void**)&Bo,   g_Bo);

    const int gemm_smem = STAGES * STAGE_BYTES;   // 110592 -> 2 CTAs/SM
    cudaFuncSetAttribute(gemm_mma_kernel, cudaFuncAttributeMaxDynamicSharedMemorySize, gemm_smem);
    const int attn_smem = (64 * 32 + 32 * 33 + 32 * 32) * 16;
    cudaFuncSetAttribute(attn_kernel, cudaFuncAttributeMaxDynamicSharedMemorySize, attn_smem);

    // operand conversion (fp16 split precision on A; B hi-only, transposed)
    split2_kernel<<<(SEQ * HIDDEN) / 256, 256>>>(hidden, Ahl, SEQ * HIDDEN);
    tsplit_kernel<<<dim3(QKVD / 32, HIDDEN / 32), dim3(32, 32)>>>(Wqkv, Bqkv, QKVD);
    tsplit_kernel<<<dim3(HIDDEN / 32, HIDDEN / 32), dim3(32, 32)>>>(Wo, Bo, HIDDEN);

    // 1) QKV projection (mma.sync fp16, 2-term split)
    gemm_mma_kernel<<<dim3(QKVD / 128, SEQ / 128), 256, gemm_smem>>>(Ahl, Bqkv, qkv_ptr, QKVD);
    // 2) RoPE
    rope_kernel<<<(SEQ * 40 * 32) / 256, 256>>>(positions);
    // 3) Causal GQA flash attention
    attn_kernel<<<dim3(SEQ / 64, NH), 256, attn_smem>>>();
    // 4) Output projection
    split2_kernel<<<(SEQ * HIDDEN) / 256, 256>>>(attn_ptr, A2hl, SEQ * HIDDEN);
    gemm_mma_kernel<<<dim3(HIDDEN / 128, SEQ / 128), 256, gemm_smem>>>(A2hl, Bo, out, HIDDEN);
}

// round 9
// speedup vs baseline: 3.0924x; 1.6509x over previous
#include <cuda_runtime.h>
#include <cuda_fp16.h>
#include <cstdint>
#include <math.h>

#define SEQ    2048
#define HIDDEN 4096
#define NH     32
#define HD     128
#define NKV    8
#define QKVD   6144
#define KOFF   4096
#define VOFF   5120
#define KA     8192    // A split-precision width: [Ah | Al]
#define KB     4096    // B width: fp16 hi only (reused for both K halves)
#define BK     64
#define NIT    128     // KA / BK
#define STAGES 3
#define ROWB   144
#define STAGE_BYTES (128 * ROWB * 2)
#define B_OFF  (128 * ROWB)
// attention smem layout
#define AROW   272     // 128 halves * 2B + 16B pad
#define Q_BYTES (128 * AROW)        // 34816
#define KV_BYTES (64 * AROW)        // 17408
#define ATTN_SMEM (Q_BYTES + 2 * (2 * KV_BYTES))  // 104448

// ---------------- scratch (__device__ globals; no allocs allowed) ----------
__device__ float  g_qkv [SEQ * QKVD];
__device__ __half g_Ahl [SEQ * KA];        // hidden split  [2048, 8192]
__device__ __half g_A2hl[SEQ * KA];        // attn out split (written by attn)
__device__ __half g_Bqkv[QKVD * KB];       // Wqkv^T hi     [6144, 4096]
__device__ __half g_Bo  [HIDDEN * KB];     // Wo^T   hi     [4096, 4096]
__device__ __half g_q16 [NH  * SEQ * HD];  // per-head packed Q (rope+scale)
__device__ __half g_k16 [NKV * SEQ * HD];  // per-kvhead packed K (rope)
__device__ __half g_v16 [NKV * SEQ * HD];  // per-kvhead packed V

__device__ __forceinline__ uint32_t smem_u32(const void* p) {
    uint32_t a;
    asm("{ .reg .u64 t; cvta.to.shared.u64 t, %1; cvt.u32.u64 %0, t; }" : "=r"(a) : "l"(p));
    return a;
}
#define CP_ASYNC16(dst, src) \
    asm volatile("cp.async.cg.shared.global [%0], [%1], 16;" :: "r"(dst), "l"(src) : "memory")

__device__ __forceinline__ void ldsm_x4(uint32_t* r, uint32_t addr) {
    asm volatile("ldmatrix.sync.aligned.m8n8.x4.shared.b16 {%0,%1,%2,%3}, [%4];"
                 : "=r"(r[0]), "=r"(r[1]), "=r"(r[2]), "=r"(r[3]) : "r"(addr));
}
__device__ __forceinline__ void ldsm_x4t(uint32_t* r, uint32_t addr) {
    asm volatile("ldmatrix.sync.aligned.m8n8.x4.trans.shared.b16 {%0,%1,%2,%3}, [%4];"
                 : "=r"(r[0]), "=r"(r[1]), "=r"(r[2]), "=r"(r[3]) : "r"(addr));
}
__device__ __forceinline__ void mma16816(float* d, const uint32_t* a, const uint32_t* b) {
    asm volatile(
        "mma.sync.aligned.m16n8k16.row.col.f32.f16.f16.f32 "
        "{%0,%1,%2,%3}, {%4,%5,%6,%7}, {%8,%9}, {%0,%1,%2,%3};"
        : "+f"(d[0]), "+f"(d[1]), "+f"(d[2]), "+f"(d[3])
        : "r"(a[0]), "r"(a[1]), "r"(a[2]), "r"(a[3]), "r"(b[0]), "r"(b[1]));
}
__device__ __forceinline__ uint32_t pack_h2(float a, float b) {
    __half2 h = __floats2half2_rn(a, b);
    return *(uint32_t*)&h;
}

// ---------------------------------------------------------------------------
// fp16 GEMM (unchanged, passing): C = A[M,KA] @ Bt[N,KB]^T
// ---------------------------------------------------------------------------
__global__ __launch_bounds__(256, 2) void gemm_mma_kernel(
    const __half* __restrict__ A,
    const __half* __restrict__ Bt,
    float* __restrict__ C, int N)
{
    extern __shared__ char smem[];
    const uint32_t sb = smem_u32(smem);
    const int tid = threadIdx.x;
    const int lane = tid & 31, warp = tid >> 5;
    const int wm = warp >> 2, wn = warp & 3;
    const int mbase = blockIdx.y * 128;
    const int nbase = blockIdx.x * 128;

    const __half* Arow = A  + (size_t)mbase * KA;
    const __half* Brow = Bt + (size_t)nbase * KB;

    const int c_row = tid >> 1;
    const int c_ch0 = (tid & 1) * 4;

    auto load_stage = [&](int itL, int stL) {
        const int kbA = itL * BK;
        const int kbB = (itL * BK) & (KB - 1);
        const uint32_t base = sb + stL * STAGE_BYTES;
        const char* asrc = (const char*)(Arow + (size_t)c_row * KA + kbA);
        const char* bsrc = (const char*)(Brow + (size_t)c_row * KB + kbB);
#pragma unroll
        for (int c = 0; c < 4; c++) {
            int ch = c_ch0 + c;
            CP_ASYNC16(base + c_row * ROWB + ch * 16,         asrc + ch * 16);
            CP_ASYNC16(base + B_OFF + c_row * ROWB + ch * 16, bsrc + ch * 16);
        }
    };

    float acc[4][4][4];
#pragma unroll
    for (int i = 0; i < 4; i++)
#pragma unroll
        for (int j = 0; j < 4; j++)
#pragma unroll
            for (int r = 0; r < 4; r++) acc[i][j][r] = 0.f;

#pragma unroll
    for (int s = 0; s < STAGES; s++) {
        load_stage(s, s);
        asm volatile("cp.async.commit_group;" ::: "memory");
    }

    const uint32_t a_row = wm * 64 + (lane & 15);
    const uint32_t a_kc  = (lane >> 4);
    const uint32_t b_row0 = wn * 32 + (lane & 7);
    const uint32_t b_half = (lane >> 4) & 1;
    const uint32_t b_kc   = (lane >> 3) & 1;

    for (int it = 0; it < NIT; it++) {
        const int st = it % 3;
        if      (it < NIT - 2)  asm volatile("cp.async.wait_group 2;" ::: "memory");
        else if (it == NIT - 2) asm volatile("cp.async.wait_group 1;" ::: "memory");
        else                    asm volatile("cp.async.wait_group 0;" ::: "memory");
        __syncthreads();

        const uint32_t abase = sb + st * STAGE_BYTES;
        const uint32_t bbase = abase + B_OFF;

#pragma unroll
        for (int s = 0; s < 4; s++) {
            uint32_t af[4][4];
#pragma unroll
            for (int i = 0; i < 4; i++)
                ldsm_x4(af[i], abase + (a_row + i * 16) * ROWB + (s * 2 + a_kc) * 16);
            uint32_t bf[4][2];
#pragma unroll
            for (int jj = 0; jj < 2; jj++) {
                uint32_t r[4];
                uint32_t brow = b_row0 + (2 * jj + b_half) * 8;
                ldsm_x4(r, bbase + brow * ROWB + (s * 2 + b_kc) * 16);
                bf[2 * jj][0] = r[0]; bf[2 * jj][1] = r[1];
                bf[2 * jj + 1][0] = r[2]; bf[2 * jj + 1][1] = r[3];
            }
#pragma unroll
            for (int i = 0; i < 4; i++)
#pragma unroll
                for (int j = 0; j < 4; j++)
                    mma16816(acc[i][j], af[i], bf[j]);
        }
        __syncthreads();

        if (it + STAGES < NIT) {
            load_stage(it + STAGES, st);
            asm volatile("cp.async.commit_group;" ::: "memory");
        }
    }

    const int g = lane >> 2, t = lane & 3;
#pragma unroll
    for (int i = 0; i < 4; i++) {
#pragma unroll
        for (int j = 0; j < 4; j++) {
            int row = mbase + wm * 64 + i * 16 + g;
            int col = nbase + wn * 32 + j * 8 + 2 * t;
            *(float2*)&C[(size_t)row * N + col] =
                make_float2(acc[i][j][0], acc[i][j][1]);
            *(float2*)&C[(size_t)(row + 8) * N + col] =
                make_float2(acc[i][j][2], acc[i][j][3]);
        }
    }
}

// ---------------------------------------------------------------------------
// fp32 -> fp16 hi/lo split for the hidden input: X[M,4096] -> Y[M,8192]
// ---------------------------------------------------------------------------
__global__ __launch_bounds__(256) void split2_kernel(
    const float* __restrict__ X, __half* __restrict__ Y, int total)
{
    int idx = blockIdx.x * blockDim.x + threadIdx.x;
    if (idx >= total) return;
    int k = idx & 4095;
    int s = idx >> 12;
    float x = X[idx];
    __half h = __float2half(x);
    __half l = __float2half(x - __half2float(h));
    size_t base = (size_t)s * KA + k;
    Y[base] = h; Y[base + 4096] = l;
}

// ---------------------------------------------------------------------------
// W [4096, N] -> Bt [N, 4096] fp16 hi, tiled transpose.
// ---------------------------------------------------------------------------
__global__ __launch_bounds__(1024) void tsplit_kernel(
    const float* __restrict__ W, __half* __restrict__ Bt, int N)
{
    __shared__ float t[32][33];
    int n0 = blockIdx.x * 32, k0 = blockIdx.y * 32;
    t[threadIdx.y][threadIdx.x] = W[(size_t)(k0 + threadIdx.y) * N + n0 + threadIdx.x];
    __syncthreads();
    float x = t[threadIdx.x][threadIdx.y];
    int n = n0 + threadIdx.y, k = k0 + threadIdx.x;
    Bt[(size_t)n * KB + k] = __float2half(x);
}

// ---------------------------------------------------------------------------
// Fused RoPE + fp16 pack: g_qkv -> g_q16/g_k16/g_v16 (Q gets 1/sqrt(HD)).
// ---------------------------------------------------------------------------
__global__ __launch_bounds__(256) void pack_rope_kernel(const int* __restrict__ pos32)
{
    int idx = blockIdx.x * blockDim.x + threadIdx.x;
    if (idx >= SEQ * QKVD) return;
    int d  = idx & 127;
    int hh = (idx >> 7) % 48;
    int s  = idx / QKVD;

    if (hh < 40) {
        int base = s * QKVD + ((hh < 32) ? hh * HD : KOFF + (hh - 32) * HD);
        float v;
        if (d < 64) {
            int j = d & 31;
            bool is64 = (pos32[1] == 0);
            int posi = is64 ? pos32[2 * s] : pos32[s];
            float inv_freq = 1.0f / powf(10000.0f, (float)j * (1.0f / 32.0f));
            float fr = (float)posi * inv_freq;
            float cs, sn;
            sincosf(fr, &sn, &cs);
            float x1 = g_qkv[base + j];
            float x2 = g_qkv[base + 32 + j];
            v = (d < 32) ? (x1 * cs - x2 * sn) : (x2 * cs + x1 * sn);
        } else {
            v = g_qkv[base + d];
        }
        if (hh < 32)
            g_q16[((size_t)hh * SEQ + s) * HD + d] = __float2half(v * 0.088388347648318447f);
        else
            g_k16[((size_t)(hh - 32) * SEQ + s) * HD + d] = __float2half(v);
    } else {
        int kvh = hh - 40;
        float v = g_qkv[s * QKVD + VOFF + kvh * HD + d];
        g_v16[((size_t)kvh * SEQ + s) * HD + d] = __float2half(v);
    }
}

// ---------------------------------------------------------------------------
// Flash attention on mma.sync fp16. CTA = (128 q-rows, head); 8 warps x 16 rows.
// ---------------------------------------------------------------------------
__global__ __launch_bounds__(256) void attn_mma_kernel()
{
    extern __shared__ char smem[];
    const uint32_t sb = smem_u32(smem);
    const uint32_t Qs = sb;
    const int tid = threadIdx.x, lane = tid & 31, warp = tid >> 5;
    const int g = lane >> 2, t4 = lane & 3;
    const int qt = gridDim.x - 1 - (int)blockIdx.x;
    const int h = blockIdx.y, kvh = h >> 2;
    const int qbase = qt * 128;
    const int qrw = warp * 16;
    const int ntiles = qt * 2 + 2;

    const __half* q16 = g_q16 + (size_t)h   * SEQ * HD;
    const __half* k16 = g_k16 + (size_t)kvh * SEQ * HD;
    const __half* v16 = g_v16 + (size_t)kvh * SEQ * HD;

#pragma unroll
    for (int i = 0; i < 8; i++) {
        int c = tid + 256 * i;
        int row = c >> 4, ch = c & 15;
        CP_ASYNC16(Qs + row * AROW + ch * 16,
                   (const char*)(q16 + (size_t)(qbase + row) * HD) + ch * 16);
    }
    auto load_kv = [&](int tt) {
        const int buf = tt & 1;
        const uint32_t Kb = sb + Q_BYTES + buf * (2 * KV_BYTES);
        const uint32_t Vb = Kb + KV_BYTES;
        const int kb = tt * 64;
#pragma unroll
        for (int i = 0; i < 4; i++) {
            int c = tid + 256 * i;
            int row = c >> 4, ch = c & 15;
            CP_ASYNC16(Kb + row * AROW + ch * 16,
                       (const char*)(k16 + (size_t)(kb + row) * HD) + ch * 16);
            CP_ASYNC16(Vb + row * AROW + ch * 16,
                       (const char*)(v16 + (size_t)(kb + row) * HD) + ch * 16);
        }
    };
    load_kv(0);
    asm volatile("cp.async.commit_group;" ::: "memory");

    float of[16][4];
#pragma unroll
    for (int i = 0; i < 16; i++)
#pragma unroll
        for (int r = 0; r < 4; r++) of[i][r] = 0.f;
    float m0 = -INFINITY, m1 = -INFINITY, l0 = 0.f, l1 = 0.f;

    const int row0 = qbase + qrw + g;

    for (int tt = 0; tt < ntiles; tt++) {
        __syncthreads();
        if (tt + 1 < ntiles) {
            load_kv(tt + 1);
            asm volatile("cp.async.commit_group;" ::: "memory");
            asm volatile("cp.async.wait_group 1;" ::: "memory");
        } else {
            asm volatile("cp.async.wait_group 0;" ::: "memory");
        }
        __syncthreads();

        const int buf = tt & 1, kb = tt * 64;
        const uint32_t Kb = sb + Q_BYTES + buf * (2 * KV_BYTES);
        const uint32_t Vb = Kb + KV_BYTES;

        // S = Q @ K^T  (16 x 64 per warp)
        float sf[8][4];
#pragma unroll
        for (int j = 0; j < 8; j++)
#pragma unroll
            for (int r = 0; r < 4; r++) sf[j][r] = 0.f;
#pragma unroll
        for (int s = 0; s < 8; s++) {
            uint32_t qf[4];
            ldsm_x4(qf, Qs + (qrw + (lane & 15)) * AROW + (s * 2 + (lane >> 4)) * 16);
#pragma unroll
            for (int jj = 0; jj < 4; jj++) {
                uint32_t kr[4];
                int brow = (lane & 7) + (2 * jj + ((lane >> 4) & 1)) * 8;
                ldsm_x4(kr, Kb + brow * AROW + (s * 2 + ((lane >> 3) & 1)) * 16);
                mma16816(sf[2 * jj],     qf, kr);
                mma16816(sf[2 * jj + 1], qf, kr + 2);
            }
        }

        // causal mask — needed whenever max col of tile exceeds MIN row of strip
        if (kb + 63 > qbase + qrw) {
#pragma unroll
            for (int j = 0; j < 8; j++) {
                int c0 = kb + j * 8 + 2 * t4;
                if (c0     > row0)     sf[j][0] = -INFINITY;
                if (c0 + 1 > row0)     sf[j][1] = -INFINITY;
                if (c0     > row0 + 8) sf[j][2] = -INFINITY;
                if (c0 + 1 > row0 + 8) sf[j][3] = -INFINITY;
            }
        }

        // online softmax (2 rows per thread; quad lanes share rows)
        float mt0 = -INFINITY, mt1 = -INFINITY;
#pragma unroll
        for (int j = 0; j < 8; j++) {
            mt0 = fmaxf(mt0, fmaxf(sf[j][0], sf[j][1]));
            mt1 = fmaxf(mt1, fmaxf(sf[j][2], sf[j][3]));
        }
        mt0 = fmaxf(mt0, __shfl_xor_sync(0xffffffffu, mt0, 1));
        mt0 = fmaxf(mt0, __shfl_xor_sync(0xffffffffu, mt0, 2));
        mt1 = fmaxf(mt1, __shfl_xor_sync(0xffffffffu, mt1, 1));
        mt1 = fmaxf(mt1, __shfl_xor_sync(0xffffffffu, mt1, 2));
        float mn0 = fmaxf(m0, mt0), mn1 = fmaxf(m1, mt1);
        float a0 = __expf(m0 - mn0), a1 = __expf(m1 - mn1);
        float s0 = 0.f, s1 = 0.f;
#pragma unroll
        for (int j = 0; j < 8; j++) {
            sf[j][0] = __expf(sf[j][0] - mn0);
            sf[j][1] = __expf(sf[j][1] - mn0);
            sf[j][2] = __expf(sf[j][2] - mn1);
            sf[j][3] = __expf(sf[j][3] - mn1);
            s0 += sf[j][0] + sf[j][1];
            s1 += sf[j][2] + sf[j][3];
        }
        s0 += __shfl_xor_sync(0xffffffffu, s0, 1);
        s0 += __shfl_xor_sync(0xffffffffu, s0, 2);
        s1 += __shfl_xor_sync(0xffffffffu, s1, 1);
        s1 += __shfl_xor_sync(0xffffffffu, s1, 2);
        l0 = l0 * a0 + s0; l1 = l1 * a1 + s1;
        m0 = mn0; m1 = mn1;
#pragma unroll
        for (int i = 0; i < 16; i++) {
            of[i][0] *= a0; of[i][1] *= a0;
            of[i][2] *= a1; of[i][3] *= a1;
        }

        // O += P @ V
#pragma unroll
        for (int c = 0; c < 4; c++) {
            uint32_t af[4];
            af[0] = pack_h2(sf[2 * c][0],     sf[2 * c][1]);
            af[1] = pack_h2(sf[2 * c][2],     sf[2 * c][3]);
            af[2] = pack_h2(sf[2 * c + 1][0], sf[2 * c + 1][1]);
            af[3] = pack_h2(sf[2 * c + 1][2], sf[2 * c + 1][3]);
#pragma unroll
            for (int d2 = 0; d2 < 8; d2++) {
                uint32_t vr[4];
                ldsm_x4t(vr, Vb + (16 * c + (lane & 15)) * AROW
                              + d2 * 32 + ((lane >> 4) & 1) * 16);
                mma16816(of[2 * d2],     af, vr);
                mma16816(of[2 * d2 + 1], af, vr + 2);
            }
        }
    }

    // write O/l as fp16 hi/lo directly into the GEMM2 A operand
    const float inv0 = 1.f / l0, inv1 = 1.f / l1;
#pragma unroll
    for (int dt = 0; dt < 16; dt++) {
        int col = h * HD + dt * 8 + 2 * t4;
        float f0 = of[dt][0] * inv0, f1 = of[dt][1] * inv0;
        float f2 = of[dt][2] * inv1, f3 = of[dt][3] * inv1;
        __half h0 = __float2half(f0), h1 = __float2half(f1);
        __half h2v = __float2half(f2), h3 = __float2half(f3);
        __half e0 = __float2half(f0 - __half2float(h0));
        __half e1 = __float2half(f1 - __half2float(h1));
        __half e2 = __float2half(f2 - __half2float(h2v));
        __half e3 = __float2half(f3 - __half2float(h3));
        size_t b0 = (size_t)row0 * KA + col;
        size_t b1 = (size_t)(row0 + 8) * KA + col;
        *(__half2*)&g_A2hl[b0]        = __halves2half2(h0, h1);
        *(__half2*)&g_A2hl[b0 + 4096] = __halves2half2(e0, e1);
        *(__half2*)&g_A2hl[b1]        = __halves2half2(h2v, h3);
        *(__half2*)&g_A2hl[b1 + 4096] = __halves2half2(e2, e3);
    }
}

// ---------------------------------------------------------------------------
extern "C" void kernel_launch(void* const* d_in, const int* in_sizes, int n_in,
                              void* d_out, int out_size)
{
    const float* hidden    = (const float*)d_in[0];
    const float* Wqkv      = (const float*)d_in[1];
    const float* Wo        = (const float*)d_in[2];
    const int*   positions = (const int*)d_in[3];
    float*       out       = (float*)d_out;

    float* qkv_ptr;
    __half *Ahl, *A2hl, *Bqkv, *Bo;
    cudaGetSymbolAddress((void**)&qkv_ptr, g_qkv);
    cudaGetSymbolAddress((void**)&Ahl,  g_Ahl);
    cudaGetSymbolAddress((void**)&A2hl, g_A2hl);
    cudaGetSymbolAddress((void**)&Bqkv, g_Bqkv);
    cudaGetSymbolAddress((void**)&Bo,   g_Bo);

    const int gemm_smem = STAGES * STAGE_BYTES;   // 110592
    cudaFuncSetAttribute(gemm_mma_kernel, cudaFuncAttributeMaxDynamicSharedMemorySize, gemm_smem);
    cudaFuncSetAttribute(attn_mma_kernel, cudaFuncAttributeMaxDynamicSharedMemorySize, ATTN_SMEM);

    // operand conversion
    split2_kernel<<<(SEQ * HIDDEN) / 256, 256>>>(hidden, Ahl, SEQ * HIDDEN);
    tsplit_kernel<<<dim3(QKVD / 32, HIDDEN / 32), dim3(32, 32)>>>(Wqkv, Bqkv, QKVD);
    tsplit_kernel<<<dim3(HIDDEN / 32, HIDDEN / 32), dim3(32, 32)>>>(Wo, Bo, HIDDEN);

    // 1) QKV projection
    gemm_mma_kernel<<<dim3(QKVD / 128, SEQ / 128), 256, gemm_smem>>>(Ahl, Bqkv, qkv_ptr, QKVD);
    // 2) fused RoPE + fp16 pack (q scaled)
    pack_rope_kernel<<<(SEQ * QKVD) / 256, 256>>>(positions);
    // 3) tensor-core flash attention -> writes g_A2hl (hi|lo) directly
    attn_mma_kernel<<<dim3(SEQ / 128, NH), 256, ATTN_SMEM>>>();
    // 4) output projection
    gemm_mma_kernel<<<dim3(HIDDEN / 128, SEQ / 128), 256, gemm_smem>>>(A2hl, Bo, out, HIDDEN);
}

// round 11
// speedup vs baseline: 3.7119x; 1.2003x over previous
#include <cuda_runtime.h>
#include <cuda_fp16.h>
#include <cstdint>
#include <math.h>

#define SEQ    2048
#define HIDDEN 4096
#define NH     32
#define HD     128
#define NKV    8
#define QKVD   6144
#define KOFF   4096
#define VOFF   5120
#define KA     8192    // GEMM1 A width: [Ah | Al]
#define KB     4096    // B width: fp16 hi only
#define BK     64
#define STAGES 3
#define ROWB   144
#define STAGE_BYTES (128 * ROWB * 2)
#define B_OFF  (128 * ROWB)
// attention smem layout
#define AROW   272
#define Q_BYTES (128 * AROW)
#define KV_BYTES (64 * AROW)
#define ATTN_SMEM (Q_BYTES + 2 * (2 * KV_BYTES))  // 104448

// ---------------- scratch (__device__ globals; no allocs allowed) ----------
__device__ float  g_qkv [SEQ * QKVD];
__device__ __half g_Ahl [SEQ * KA];        // hidden split  [2048, 8192]
__device__ __half g_A2  [SEQ * KB];        // attn out (hi only) [2048, 4096]
__device__ __half g_Bqkv[QKVD * KB];       // Wqkv^T hi     [6144, 4096]
__device__ __half g_Bo  [HIDDEN * KB];     // Wo^T   hi     [4096, 4096]
__device__ __half g_q16 [NH  * SEQ * HD];
__device__ __half g_k16 [NKV * SEQ * HD];
__device__ __half g_v16 [NKV * SEQ * HD];

__device__ __forceinline__ uint32_t smem_u32(const void* p) {
    uint32_t a;
    asm("{ .reg .u64 t; cvta.to.shared.u64 t, %1; cvt.u32.u64 %0, t; }" : "=r"(a) : "l"(p));
    return a;
}
#define CP_ASYNC16(dst, src) \
    asm volatile("cp.async.cg.shared.global [%0], [%1], 16;" :: "r"(dst), "l"(src) : "memory")

__device__ __forceinline__ void ldsm_x4(uint32_t* r, uint32_t addr) {
    asm volatile("ldmatrix.sync.aligned.m8n8.x4.shared.b16 {%0,%1,%2,%3}, [%4];"
                 : "=r"(r[0]), "=r"(r[1]), "=r"(r[2]), "=r"(r[3]) : "r"(addr));
}
__device__ __forceinline__ void ldsm_x4t(uint32_t* r, uint32_t addr) {
    asm volatile("ldmatrix.sync.aligned.m8n8.x4.trans.shared.b16 {%0,%1,%2,%3}, [%4];"
                 : "=r"(r[0]), "=r"(r[1]), "=r"(r[2]), "=r"(r[3]) : "r"(addr));
}
__device__ __forceinline__ void mma16816(float* d, const uint32_t* a, const uint32_t* b) {
    asm volatile(
        "mma.sync.aligned.m16n8k16.row.col.f32.f16.f16.f32 "
        "{%0,%1,%2,%3}, {%4,%5,%6,%7}, {%8,%9}, {%0,%1,%2,%3};"
        : "+f"(d[0]), "+f"(d[1]), "+f"(d[2]), "+f"(d[3])
        : "r"(a[0]), "r"(a[1]), "r"(a[2]), "r"(a[3]), "r"(b[0]), "r"(b[1]));
}
__device__ __forceinline__ uint32_t pack_h2(float a, float b) {
    __half2 h = __floats2half2_rn(a, b);
    return *(uint32_t*)&h;
}

// ---------------------------------------------------------------------------
// fp16 GEMM: C[M,N] = A[M,Ka] @ Bt[N,KB]^T over nIter*BK k-columns.
// B wraps every KB columns (used by the split-precision GEMM1).
// ---------------------------------------------------------------------------
__global__ __launch_bounds__(256, 2) void gemm_mma_kernel(
    const __half* __restrict__ A,
    const __half* __restrict__ Bt,
    float* __restrict__ C, int N, int Ka, int nIter)
{
    extern __shared__ char smem[];
    const uint32_t sb = smem_u32(smem);
    const int tid = threadIdx.x;
    const int lane = tid & 31, warp = tid >> 5;
    const int wm = warp >> 2, wn = warp & 3;
    const int mbase = blockIdx.y * 128;
    const int nbase = blockIdx.x * 128;

    const __half* Arow = A  + (size_t)mbase * Ka;
    const __half* Brow = Bt + (size_t)nbase * KB;

    const int c_row = tid >> 1;
    const int c_ch0 = (tid & 1) * 4;

    auto load_stage = [&](int itL, int stL) {
        const int kbA = itL * BK;
        const int kbB = (itL * BK) & (KB - 1);
        const uint32_t base = sb + stL * STAGE_BYTES;
        const char* asrc = (const char*)(Arow + (size_t)c_row * Ka + kbA);
        const char* bsrc = (const char*)(Brow + (size_t)c_row * KB + kbB);
#pragma unroll
        for (int c = 0; c < 4; c++) {
            int ch = c_ch0 + c;
            CP_ASYNC16(base + c_row * ROWB + ch * 16,         asrc + ch * 16);
            CP_ASYNC16(base + B_OFF + c_row * ROWB + ch * 16, bsrc + ch * 16);
        }
    };

    float acc[4][4][4];
#pragma unroll
    for (int i = 0; i < 4; i++)
#pragma unroll
        for (int j = 0; j < 4; j++)
#pragma unroll
            for (int r = 0; r < 4; r++) acc[i][j][r] = 0.f;

#pragma unroll
    for (int s = 0; s < STAGES; s++) {
        load_stage(s, s);
        asm volatile("cp.async.commit_group;" ::: "memory");
    }

    const uint32_t a_row = wm * 64 + (lane & 15);
    const uint32_t a_kc  = (lane >> 4);
    const uint32_t b_row0 = wn * 32 + (lane & 7);
    const uint32_t b_half = (lane >> 4) & 1;
    const uint32_t b_kc   = (lane >> 3) & 1;

    for (int it = 0; it < nIter; it++) {
        const int st = it % 3;
        if      (it < nIter - 2)  asm volatile("cp.async.wait_group 2;" ::: "memory");
        else if (it == nIter - 2) asm volatile("cp.async.wait_group 1;" ::: "memory");
        else                      asm volatile("cp.async.wait_group 0;" ::: "memory");
        __syncthreads();

        const uint32_t abase = sb + st * STAGE_BYTES;
        const uint32_t bbase = abase + B_OFF;

#pragma unroll
        for (int s = 0; s < 4; s++) {
            uint32_t af[4][4];
#pragma unroll
            for (int i = 0; i < 4; i++)
                ldsm_x4(af[i], abase + (a_row + i * 16) * ROWB + (s * 2 + a_kc) * 16);
            uint32_t bf[4][2];
#pragma unroll
            for (int jj = 0; jj < 2; jj++) {
                uint32_t r[4];
                uint32_t brow = b_row0 + (2 * jj + b_half) * 8;
                ldsm_x4(r, bbase + brow * ROWB + (s * 2 + b_kc) * 16);
                bf[2 * jj][0] = r[0]; bf[2 * jj][1] = r[1];
                bf[2 * jj + 1][0] = r[2]; bf[2 * jj + 1][1] = r[3];
            }
#pragma unroll
            for (int i = 0; i < 4; i++)
#pragma unroll
                for (int j = 0; j < 4; j++)
                    mma16816(acc[i][j], af[i], bf[j]);
        }
        __syncthreads();

        if (it + STAGES < nIter) {
            load_stage(it + STAGES, st);
            asm volatile("cp.async.commit_group;" ::: "memory");
        }
    }

    const int g = lane >> 2, t = lane & 3;
#pragma unroll
    for (int i = 0; i < 4; i++) {
#pragma unroll
        for (int j = 0; j < 4; j++) {
            int row = mbase + wm * 64 + i * 16 + g;
            int col = nbase + wn * 32 + j * 8 + 2 * t;
            *(float2*)&C[(size_t)row * N + col] =
                make_float2(acc[i][j][0], acc[i][j][1]);
            *(float2*)&C[(size_t)(row + 8) * N + col] =
                make_float2(acc[i][j][2], acc[i][j][3]);
        }
    }
}

// ---------------------------------------------------------------------------
// fp32 -> fp16 hi/lo split for the hidden input: X[M,4096] -> Y[M,8192]
// ---------------------------------------------------------------------------
__global__ __launch_bounds__(256) void split2_kernel(
    const float* __restrict__ X, __half* __restrict__ Y, int total)
{
    int idx = blockIdx.x * blockDim.x + threadIdx.x;
    if (idx >= total) return;
    int k = idx & 4095;
    int s = idx >> 12;
    float x = X[idx];
    __half h = __float2half(x);
    __half l = __float2half(x - __half2float(h));
    size_t base = (size_t)s * KA + k;
    Y[base] = h; Y[base + 4096] = l;
}

// ---------------------------------------------------------------------------
// W [4096, N] -> Bt [N, 4096] fp16 hi, tiled transpose.
// ---------------------------------------------------------------------------
__global__ __launch_bounds__(1024) void tsplit_kernel(
    const float* __restrict__ W, __half* __restrict__ Bt, int N)
{
    __shared__ float t[32][33];
    int n0 = blockIdx.x * 32, k0 = blockIdx.y * 32;
    t[threadIdx.y][threadIdx.x] = W[(size_t)(k0 + threadIdx.y) * N + n0 + threadIdx.x];
    __syncthreads();
    float x = t[threadIdx.x][threadIdx.y];
    int n = n0 + threadIdx.y, k = k0 + threadIdx.x;
    Bt[(size_t)n * KB + k] = __float2half(x);
}

// ---------------------------------------------------------------------------
// Fused RoPE + fp16 pack: g_qkv -> g_q16/g_k16/g_v16 (Q gets 1/sqrt(HD)).
// ---------------------------------------------------------------------------
__global__ __launch_bounds__(256) void pack_rope_kernel(const int* __restrict__ pos32)
{
    int idx = blockIdx.x * blockDim.x + threadIdx.x;
    if (idx >= SEQ * QKVD) return;
    int d  = idx & 127;
    int hh = (idx >> 7) % 48;
    int s  = idx / QKVD;

    if (hh < 40) {
        int base = s * QKVD + ((hh < 32) ? hh * HD : KOFF + (hh - 32) * HD);
        float v;
        if (d < 64) {
            int j = d & 31;
            bool is64 = (pos32[1] == 0);
            int posi = is64 ? pos32[2 * s] : pos32[s];
            float inv_freq = 1.0f / powf(10000.0f, (float)j * (1.0f / 32.0f));
            float fr = (float)posi * inv_freq;
            float cs, sn;
            sincosf(fr, &sn, &cs);
            float x1 = g_qkv[base + j];
            float x2 = g_qkv[base + 32 + j];
            v = (d < 32) ? (x1 * cs - x2 * sn) : (x2 * cs + x1 * sn);
        } else {
            v = g_qkv[base + d];
        }
        if (hh < 32)
            g_q16[((size_t)hh * SEQ + s) * HD + d] = __float2half(v * 0.088388347648318447f);
        else
            g_k16[((size_t)(hh - 32) * SEQ + s) * HD + d] = __float2half(v);
    } else {
        int kvh = hh - 40;
        float v = g_qkv[s * QKVD + VOFF + kvh * HD + d];
        g_v16[((size_t)kvh * SEQ + s) * HD + d] = __float2half(v);
    }
}

// ---------------------------------------------------------------------------
// Flash attention on mma.sync fp16 (passing). Output: fp16 hi into g_A2.
// ---------------------------------------------------------------------------
__global__ __launch_bounds__(256) void attn_mma_kernel()
{
    extern __shared__ char smem[];
    const uint32_t sb = smem_u32(smem);
    const uint32_t Qs = sb;
    const int tid = threadIdx.x, lane = tid & 31, warp = tid >> 5;
    const int g = lane >> 2, t4 = lane & 3;
    const int qt = gridDim.x - 1 - (int)blockIdx.x;
    const int h = blockIdx.y, kvh = h >> 2;
    const int qbase = qt * 128;
    const int qrw = warp * 16;
    const int ntiles = qt * 2 + 2;

    const __half* q16 = g_q16 + (size_t)h   * SEQ * HD;
    const __half* k16 = g_k16 + (size_t)kvh * SEQ * HD;
    const __half* v16 = g_v16 + (size_t)kvh * SEQ * HD;

#pragma unroll
    for (int i = 0; i < 8; i++) {
        int c = tid + 256 * i;
        int row = c >> 4, ch = c & 15;
        CP_ASYNC16(Qs + row * AROW + ch * 16,
                   (const char*)(q16 + (size_t)(qbase + row) * HD) + ch * 16);
    }
    auto load_kv = [&](int tt) {
        const int buf = tt & 1;
        const uint32_t Kb = sb + Q_BYTES + buf * (2 * KV_BYTES);
        const uint32_t Vb = Kb + KV_BYTES;
        const int kb = tt * 64;
#pragma unroll
        for (int i = 0; i < 4; i++) {
            int c = tid + 256 * i;
            int row = c >> 4, ch = c & 15;
            CP_ASYNC16(Kb + row * AROW + ch * 16,
                       (const char*)(k16 + (size_t)(kb + row) * HD) + ch * 16);
            CP_ASYNC16(Vb + row * AROW + ch * 16,
                       (const char*)(v16 + (size_t)(kb + row) * HD) + ch * 16);
        }
    };
    load_kv(0);
    asm volatile("cp.async.commit_group;" ::: "memory");

    float of[16][4];
#pragma unroll
    for (int i = 0; i < 16; i++)
#pragma unroll
        for (int r = 0; r < 4; r++) of[i][r] = 0.f;
    float m0 = -INFINITY, m1 = -INFINITY, l0 = 0.f, l1 = 0.f;

    const int row0 = qbase + qrw + g;

    for (int tt = 0; tt < ntiles; tt++) {
        __syncthreads();
        if (tt + 1 < ntiles) {
            load_kv(tt + 1);
            asm volatile("cp.async.commit_group;" ::: "memory");
            asm volatile("cp.async.wait_group 1;" ::: "memory");
        } else {
            asm volatile("cp.async.wait_group 0;" ::: "memory");
        }
        __syncthreads();

        const int buf = tt & 1, kb = tt * 64;
        const uint32_t Kb = sb + Q_BYTES + buf * (2 * KV_BYTES);
        const uint32_t Vb = Kb + KV_BYTES;

        float sf[8][4];
#pragma unroll
        for (int j = 0; j < 8; j++)
#pragma unroll
            for (int r = 0; r < 4; r++) sf[j][r] = 0.f;
#pragma unroll
        for (int s = 0; s < 8; s++) {
            uint32_t qf[4];
            ldsm_x4(qf, Qs + (qrw + (lane & 15)) * AROW + (s * 2 + (lane >> 4)) * 16);
#pragma unroll
            for (int jj = 0; jj < 4; jj++) {
                uint32_t kr[4];
                int brow = (lane & 7) + (2 * jj + ((lane >> 4) & 1)) * 8;
                ldsm_x4(kr, Kb + brow * AROW + (s * 2 + ((lane >> 3) & 1)) * 16);
                mma16816(sf[2 * jj],     qf, kr);
                mma16816(sf[2 * jj + 1], qf, kr + 2);
            }
        }

        // causal mask — needed whenever max col of tile exceeds MIN row of strip
        if (kb + 63 > qbase + qrw) {
#pragma unroll
            for (int j = 0; j < 8; j++) {
                int c0 = kb + j * 8 + 2 * t4;
                if (c0     > row0)     sf[j][0] = -INFINITY;
                if (c0 + 1 > row0)     sf[j][1] = -INFINITY;
                if (c0     > row0 + 8) sf[j][2] = -INFINITY;
                if (c0 + 1 > row0 + 8) sf[j][3] = -INFINITY;
            }
        }

        float mt0 = -INFINITY, mt1 = -INFINITY;
#pragma unroll
        for (int j = 0; j < 8; j++) {
            mt0 = fmaxf(mt0, fmaxf(sf[j][0], sf[j][1]));
            mt1 = fmaxf(mt1, fmaxf(sf[j][2], sf[j][3]));
        }
        mt0 = fmaxf(mt0, __shfl_xor_sync(0xffffffffu, mt0, 1));
        mt0 = fmaxf(mt0, __shfl_xor_sync(0xffffffffu, mt0, 2));
        mt1 = fmaxf(mt1, __shfl_xor_sync(0xffffffffu, mt1, 1));
        mt1 = fmaxf(mt1, __shfl_xor_sync(0xffffffffu, mt1, 2));
        float mn0 = fmaxf(m0, mt0), mn1 = fmaxf(m1, mt1);
        float a0 = __expf(m0 - mn0), a1 = __expf(m1 - mn1);
        float s0 = 0.f, s1 = 0.f;
#pragma unroll
        for (int j = 0; j < 8; j++) {
            sf[j][0] = __expf(sf[j][0] - mn0);
            sf[j][1] = __expf(sf[j][1] - mn0);
            sf[j][2] = __expf(sf[j][2] - mn1);
            sf[j][3] = __expf(sf[j][3] - mn1);
            s0 += sf[j][0] + sf[j][1];
            s1 += sf[j][2] + sf[j][3];
        }
        s0 += __shfl_xor_sync(0xffffffffu, s0, 1);
        s0 += __shfl_xor_sync(0xffffffffu, s0, 2);
        s1 += __shfl_xor_sync(0xffffffffu, s1, 1);
        s1 += __shfl_xor_sync(0xffffffffu, s1, 2);
        l0 = l0 * a0 + s0; l1 = l1 * a1 + s1;
        m0 = mn0; m1 = mn1;
#pragma unroll
        for (int i = 0; i < 16; i++) {
            of[i][0] *= a0; of[i][1] *= a0;
            of[i][2] *= a1; of[i][3] *= a1;
        }

#pragma unroll
        for (int c = 0; c < 4; c++) {
            uint32_t af[4];
            af[0] = pack_h2(sf[2 * c][0],     sf[2 * c][1]);
            af[1] = pack_h2(sf[2 * c][2],     sf[2 * c][3]);
            af[2] = pack_h2(sf[2 * c + 1][0], sf[2 * c + 1][1]);
            af[3] = pack_h2(sf[2 * c + 1][2], sf[2 * c + 1][3]);
#pragma unroll
            for (int d2 = 0; d2 < 8; d2++) {
                uint32_t vr[4];
                ldsm_x4t(vr, Vb + (16 * c + (lane & 15)) * AROW
                              + d2 * 32 + ((lane >> 4) & 1) * 16);
                mma16816(of[2 * d2],     af, vr);
                mma16816(of[2 * d2 + 1], af, vr + 2);
            }
        }
    }

    // write O (fp16 hi only) into the GEMM2 A operand [2048, 4096]
    const float inv0 = 1.f / l0, inv1 = 1.f / l1;
#pragma unroll
    for (int dt = 0; dt < 16; dt++) {
        int col = h * HD + dt * 8 + 2 * t4;
        *(__half2*)&g_A2[(size_t)row0 * KB + col] =
            __floats2half2_rn(of[dt][0] * inv0, of[dt][1] * inv0);
        *(__half2*)&g_A2[(size_t)(row0 + 8) * KB + col] =
            __floats2half2_rn(of[dt][2] * inv1, of[dt][3] * inv1);
    }
}

// ---------------------------------------------------------------------------
extern "C" void kernel_launch(void* const* d_in, const int* in_sizes, int n_in,
                              void* d_out, int out_size)
{
    const float* hidden    = (const float*)d_in[0];
    const float* Wqkv      = (const float*)d_in[1];
    const float* Wo        = (const float*)d_in[2];
    const int*   positions = (const int*)d_in[3];
    float*       out       = (float*)d_out;

    float* qkv_ptr;
    __half *Ahl, *A2, *Bqkv, *Bo;
    cudaGetSymbolAddress((void**)&qkv_ptr, g_qkv);
    cudaGetSymbolAddress((void**)&Ahl,  g_Ahl);
    cudaGetSymbolAddress((void**)&A2,   g_A2);
    cudaGetSymbolAddress((void**)&Bqkv, g_Bqkv);
    cudaGetSymbolAddress((void**)&Bo,   g_Bo);

    const int gemm_smem = STAGES * STAGE_BYTES;   // 110592
    cudaFuncSetAttribute(gemm_mma_kernel, cudaFuncAttributeMaxDynamicSharedMemorySize, gemm_smem);
    cudaFuncSetAttribute(attn_mma_kernel, cudaFuncAttributeMaxDynamicSharedMemorySize, ATTN_SMEM);

    // operand conversion
    split2_kernel<<<(SEQ * HIDDEN) / 256, 256>>>(hidden, Ahl, SEQ * HIDDEN);
    tsplit_kernel<<<dim3(QKVD / 32, HIDDEN / 32), dim3(32, 32)>>>(Wqkv, Bqkv, QKVD);
    tsplit_kernel<<<dim3(HIDDEN / 32, HIDDEN / 32), dim3(32, 32)>>>(Wo, Bo, HIDDEN);

    // 1) QKV projection: split-precision (K = 8192, B wraps)
    gemm_mma_kernel<<<dim3(QKVD / 128, SEQ / 128), 256, gemm_smem>>>(
        Ahl, Bqkv, qkv_ptr, QKVD, KA, KA / BK);
    // 2) fused RoPE + fp16 pack (q scaled)
    pack_rope_kernel<<<(SEQ * QKVD) / 256, 256>>>(positions);
    // 3) tensor-core flash attention -> g_A2 (fp16 hi)
    attn_mma_kernel<<<dim3(SEQ / 128, NH), 256, ATTN_SMEM>>>();
    // 4) output projection: hi-only (K = 4096)
    gemm_mma_kernel<<<dim3(HIDDEN / 128, SEQ / 128), 256, gemm_smem>>>(
        A2, Bo, out, HIDDEN, KB, KB / BK);
}

// round 12
// speedup vs baseline: 5.1467x; 1.3865x over previous
#include <cuda_runtime.h>
#include <cuda_fp16.h>
#include <cstdint>
#include <math.h>

#define SEQ    2048
#define HIDDEN 4096
#define NH     32
#define HD     128
#define NKV    8
#define QKVD   6144
#define KOFF   4096
#define VOFF   5120
#define KB     4096    // all GEMM operands: fp16 hi only, K = 4096
#define BK     64
#define STAGES 3
#define ROWB   144
#define STAGE_BYTES (128 * ROWB * 2)
#define B_OFF  (128 * ROWB)
// attention smem layout
#define AROW   272
#define Q_BYTES (128 * AROW)
#define KV_BYTES (64 * AROW)
#define ATTN_SMEM (Q_BYTES + 2 * (2 * KV_BYTES))  // 104448

// ---------------- scratch (__device__ globals; no allocs allowed) ----------
__device__ float  g_qkv [SEQ * QKVD];
__device__ __half g_A1  [SEQ * KB];        // hidden (hi)   [2048, 4096]
__device__ __half g_A2  [SEQ * KB];        // attn out (hi) [2048, 4096]
__device__ __half g_Bqkv[QKVD * KB];       // Wqkv^T hi     [6144, 4096]
__device__ __half g_Bo  [HIDDEN * KB];     // Wo^T   hi     [4096, 4096]
__device__ __half g_q16 [NH  * SEQ * HD];
__device__ __half g_k16 [NKV * SEQ * HD];
__device__ __half g_v16 [NKV * SEQ * HD];

__device__ __forceinline__ uint32_t smem_u32(const void* p) {
    uint32_t a;
    asm("{ .reg .u64 t; cvta.to.shared.u64 t, %1; cvt.u32.u64 %0, t; }" : "=r"(a) : "l"(p));
    return a;
}
#define CP_ASYNC16(dst, src) \
    asm volatile("cp.async.cg.shared.global [%0], [%1], 16;" :: "r"(dst), "l"(src) : "memory")

__device__ __forceinline__ void ldsm_x4(uint32_t* r, uint32_t addr) {
    asm volatile("ldmatrix.sync.aligned.m8n8.x4.shared.b16 {%0,%1,%2,%3}, [%4];"
                 : "=r"(r[0]), "=r"(r[1]), "=r"(r[2]), "=r"(r[3]) : "r"(addr));
}
__device__ __forceinline__ void ldsm_x4t(uint32_t* r, uint32_t addr) {
    asm volatile("ldmatrix.sync.aligned.m8n8.x4.trans.shared.b16 {%0,%1,%2,%3}, [%4];"
                 : "=r"(r[0]), "=r"(r[1]), "=r"(r[2]), "=r"(r[3]) : "r"(addr));
}
__device__ __forceinline__ void mma16816(float* d, const uint32_t* a, const uint32_t* b) {
    asm volatile(
        "mma.sync.aligned.m16n8k16.row.col.f32.f16.f16.f32 "
        "{%0,%1,%2,%3}, {%4,%5,%6,%7}, {%8,%9}, {%0,%1,%2,%3};"
        : "+f"(d[0]), "+f"(d[1]), "+f"(d[2]), "+f"(d[3])
        : "r"(a[0]), "r"(a[1]), "r"(a[2]), "r"(a[3]), "r"(b[0]), "r"(b[1]));
}
__device__ __forceinline__ uint32_t pack_h2(float a, float b) {
    __half2 h = __floats2half2_rn(a, b);
    return *(uint32_t*)&h;
}

// ---------------------------------------------------------------------------
// fp16 GEMM: C[M,N] = A[M,KB] @ Bt[N,KB]^T  (64 k-iterations)
// BM=BN=128, BK=64, 256 threads, 3-stage cp.async, 2 CTA/SM.
// ---------------------------------------------------------------------------
__global__ __launch_bounds__(256, 2) void gemm_mma_kernel(
    const __half* __restrict__ A,
    const __half* __restrict__ Bt,
    float* __restrict__ C, int N)
{
    extern __shared__ char smem[];
    const uint32_t sb = smem_u32(smem);
    const int tid = threadIdx.x;
    const int lane = tid & 31, warp = tid >> 5;
    const int wm = warp >> 2, wn = warp & 3;
    const int mbase = blockIdx.y * 128;
    const int nbase = blockIdx.x * 128;
    const int nIter = KB / BK;   // 64

    const __half* Arow = A  + (size_t)mbase * KB;
    const __half* Brow = Bt + (size_t)nbase * KB;

    const int c_row = tid >> 1;
    const int c_ch0 = (tid & 1) * 4;

    auto load_stage = [&](int itL, int stL) {
        const int kb = itL * BK;
        const uint32_t base = sb + stL * STAGE_BYTES;
        const char* asrc = (const char*)(Arow + (size_t)c_row * KB + kb);
        const char* bsrc = (const char*)(Brow + (size_t)c_row * KB + kb);
#pragma unroll
        for (int c = 0; c < 4; c++) {
            int ch = c_ch0 + c;
            CP_ASYNC16(base + c_row * ROWB + ch * 16,         asrc + ch * 16);
            CP_ASYNC16(base + B_OFF + c_row * ROWB + ch * 16, bsrc + ch * 16);
        }
    };

    float acc[4][4][4];
#pragma unroll
    for (int i = 0; i < 4; i++)
#pragma unroll
        for (int j = 0; j < 4; j++)
#pragma unroll
            for (int r = 0; r < 4; r++) acc[i][j][r] = 0.f;

#pragma unroll
    for (int s = 0; s < STAGES; s++) {
        load_stage(s, s);
        asm volatile("cp.async.commit_group;" ::: "memory");
    }

    const uint32_t a_row = wm * 64 + (lane & 15);
    const uint32_t a_kc  = (lane >> 4);
    const uint32_t b_row0 = wn * 32 + (lane & 7);
    const uint32_t b_half = (lane >> 4) & 1;
    const uint32_t b_kc   = (lane >> 3) & 1;

    for (int it = 0; it < nIter; it++) {
        const int st = it % 3;
        if      (it < nIter - 2)  asm volatile("cp.async.wait_group 2;" ::: "memory");
        else if (it == nIter - 2) asm volatile("cp.async.wait_group 1;" ::: "memory");
        else                      asm volatile("cp.async.wait_group 0;" ::: "memory");
        __syncthreads();

        const uint32_t abase = sb + st * STAGE_BYTES;
        const uint32_t bbase = abase + B_OFF;

#pragma unroll
        for (int s = 0; s < 4; s++) {
            uint32_t af[4][4];
#pragma unroll
            for (int i = 0; i < 4; i++)
                ldsm_x4(af[i], abase + (a_row + i * 16) * ROWB + (s * 2 + a_kc) * 16);
            uint32_t bf[4][2];
#pragma unroll
            for (int jj = 0; jj < 2; jj++) {
                uint32_t r[4];
                uint32_t brow = b_row0 + (2 * jj + b_half) * 8;
                ldsm_x4(r, bbase + brow * ROWB + (s * 2 + b_kc) * 16);
                bf[2 * jj][0] = r[0]; bf[2 * jj][1] = r[1];
                bf[2 * jj + 1][0] = r[2]; bf[2 * jj + 1][1] = r[3];
            }
#pragma unroll
            for (int i = 0; i < 4; i++)
#pragma unroll
                for (int j = 0; j < 4; j++)
                    mma16816(acc[i][j], af[i], bf[j]);
        }
        __syncthreads();

        if (it + STAGES < nIter) {
            load_stage(it + STAGES, st);
            asm volatile("cp.async.commit_group;" ::: "memory");
        }
    }

    const int g = lane >> 2, t = lane & 3;
#pragma unroll
    for (int i = 0; i < 4; i++) {
#pragma unroll
        for (int j = 0; j < 4; j++) {
            int row = mbase + wm * 64 + i * 16 + g;
            int col = nbase + wn * 32 + j * 8 + 2 * t;
            *(float2*)&C[(size_t)row * N + col] =
                make_float2(acc[i][j][0], acc[i][j][1]);
            *(float2*)&C[(size_t)(row + 8) * N + col] =
                make_float2(acc[i][j][2], acc[i][j][3]);
        }
    }
}

// ---------------------------------------------------------------------------
// fp32 -> fp16 convert (hi only): X[M,4096] -> Y[M,4096]
// ---------------------------------------------------------------------------
__global__ __launch_bounds__(256) void cvt_kernel(
    const float* __restrict__ X, __half* __restrict__ Y, int total)
{
    int idx = blockIdx.x * blockDim.x + threadIdx.x;
    if (idx >= total) return;
    Y[idx] = __float2half(X[idx]);
}

// ---------------------------------------------------------------------------
// W [4096, N] -> Bt [N, 4096] fp16 hi, tiled transpose.
// ---------------------------------------------------------------------------
__global__ __launch_bounds__(1024) void tsplit_kernel(
    const float* __restrict__ W, __half* __restrict__ Bt, int N)
{
    __shared__ float t[32][33];
    int n0 = blockIdx.x * 32, k0 = blockIdx.y * 32;
    t[threadIdx.y][threadIdx.x] = W[(size_t)(k0 + threadIdx.y) * N + n0 + threadIdx.x];
    __syncthreads();
    float x = t[threadIdx.x][threadIdx.y];
    int n = n0 + threadIdx.y, k = k0 + threadIdx.x;
    Bt[(size_t)n * KB + k] = __float2half(x);
}

// ---------------------------------------------------------------------------
// Fused RoPE + fp16 pack: g_qkv -> g_q16/g_k16/g_v16 (Q gets 1/sqrt(HD)).
// ---------------------------------------------------------------------------
__global__ __launch_bounds__(256) void pack_rope_kernel(const int* __restrict__ pos32)
{
    int idx = blockIdx.x * blockDim.x + threadIdx.x;
    if (idx >= SEQ * QKVD) return;
    int d  = idx & 127;
    int hh = (idx >> 7) % 48;
    int s  = idx / QKVD;

    if (hh < 40) {
        int base = s * QKVD + ((hh < 32) ? hh * HD : KOFF + (hh - 32) * HD);
        float v;
        if (d < 64) {
            int j = d & 31;
            bool is64 = (pos32[1] == 0);
            int posi = is64 ? pos32[2 * s] : pos32[s];
            float inv_freq = 1.0f / powf(10000.0f, (float)j * (1.0f / 32.0f));
            float fr = (float)posi * inv_freq;
            float cs, sn;
            sincosf(fr, &sn, &cs);
            float x1 = g_qkv[base + j];
            float x2 = g_qkv[base + 32 + j];
            v = (d < 32) ? (x1 * cs - x2 * sn) : (x2 * cs + x1 * sn);
        } else {
            v = g_qkv[base + d];
        }
        if (hh < 32)
            g_q16[((size_t)hh * SEQ + s) * HD + d] = __float2half(v * 0.088388347648318447f);
        else
            g_k16[((size_t)(hh - 32) * SEQ + s) * HD + d] = __float2half(v);
    } else {
        int kvh = hh - 40;
        float v = g_qkv[s * QKVD + VOFF + kvh * HD + d];
        g_v16[((size_t)kvh * SEQ + s) * HD + d] = __float2half(v);
    }
}

// ---------------------------------------------------------------------------
// Flash attention on mma.sync fp16 (passing). Output: fp16 hi into g_A2.
// ---------------------------------------------------------------------------
__global__ __launch_bounds__(256) void attn_mma_kernel()
{
    extern __shared__ char smem[];
    const uint32_t sb = smem_u32(smem);
    const uint32_t Qs = sb;
    const int tid = threadIdx.x, lane = tid & 31, warp = tid >> 5;
    const int g = lane >> 2, t4 = lane & 3;
    const int qt = gridDim.x - 1 - (int)blockIdx.x;
    const int h = blockIdx.y, kvh = h >> 2;
    const int qbase = qt * 128;
    const int qrw = warp * 16;
    const int ntiles = qt * 2 + 2;

    const __half* q16 = g_q16 + (size_t)h   * SEQ * HD;
    const __half* k16 = g_k16 + (size_t)kvh * SEQ * HD;
    const __half* v16 = g_v16 + (size_t)kvh * SEQ * HD;

#pragma unroll
    for (int i = 0; i < 8; i++) {
        int c = tid + 256 * i;
        int row = c >> 4, ch = c & 15;
        CP_ASYNC16(Qs + row * AROW + ch * 16,
                   (const char*)(q16 + (size_t)(qbase + row) * HD) + ch * 16);
    }
    auto load_kv = [&](int tt) {
        const int buf = tt & 1;
        const uint32_t Kb = sb + Q_BYTES + buf * (2 * KV_BYTES);
        const uint32_t Vb = Kb + KV_BYTES;
        const int kb = tt * 64;
#pragma unroll
        for (int i = 0; i < 4; i++) {
            int c = tid + 256 * i;
            int row = c >> 4, ch = c & 15;
            CP_ASYNC16(Kb + row * AROW + ch * 16,
                       (const char*)(k16 + (size_t)(kb + row) * HD) + ch * 16);
            CP_ASYNC16(Vb + row * AROW + ch * 16,
                       (const char*)(v16 + (size_t)(kb + row) * HD) + ch * 16);
        }
    };
    load_kv(0);
    asm volatile("cp.async.commit_group;" ::: "memory");

    float of[16][4];
#pragma unroll
    for (int i = 0; i < 16; i++)
#pragma unroll
        for (int r = 0; r < 4; r++) of[i][r] = 0.f;
    float m0 = -INFINITY, m1 = -INFINITY, l0 = 0.f, l1 = 0.f;

    const int row0 = qbase + qrw + g;

    for (int tt = 0; tt < ntiles; tt++) {
        __syncthreads();
        if (tt + 1 < ntiles) {
            load_kv(tt + 1);
            asm volatile("cp.async.commit_group;" ::: "memory");
            asm volatile("cp.async.wait_group 1;" ::: "memory");
        } else {
            asm volatile("cp.async.wait_group 0;" ::: "memory");
        }
        __syncthreads();

        const int buf = tt & 1, kb = tt * 64;
        const uint32_t Kb = sb + Q_BYTES + buf * (2 * KV_BYTES);
        const uint32_t Vb = Kb + KV_BYTES;

        float sf[8][4];
#pragma unroll
        for (int j = 0; j < 8; j++)
#pragma unroll
            for (int r = 0; r < 4; r++) sf[j][r] = 0.f;
#pragma unroll
        for (int s = 0; s < 8; s++) {
            uint32_t qf[4];
            ldsm_x4(qf, Qs + (qrw + (lane & 15)) * AROW + (s * 2 + (lane >> 4)) * 16);
#pragma unroll
            for (int jj = 0; jj < 4; jj++) {
                uint32_t kr[4];
                int brow = (lane & 7) + (2 * jj + ((lane >> 4) & 1)) * 8;
                ldsm_x4(kr, Kb + brow * AROW + (s * 2 + ((lane >> 3) & 1)) * 16);
                mma16816(sf[2 * jj],     qf, kr);
                mma16816(sf[2 * jj + 1], qf, kr + 2);
            }
        }

        // causal mask — needed whenever max col of tile exceeds MIN row of strip
        if (kb + 63 > qbase + qrw) {
#pragma unroll
            for (int j = 0; j < 8; j++) {
                int c0 = kb + j * 8 + 2 * t4;
                if (c0     > row0)     sf[j][0] = -INFINITY;
                if (c0 + 1 > row0)     sf[j][1] = -INFINITY;
                if (c0     > row0 + 8) sf[j][2] = -INFINITY;
                if (c0 + 1 > row0 + 8) sf[j][3] = -INFINITY;
            }
        }

        float mt0 = -INFINITY, mt1 = -INFINITY;
#pragma unroll
        for (int j = 0; j < 8; j++) {
            mt0 = fmaxf(mt0, fmaxf(sf[j][0], sf[j][1]));
            mt1 = fmaxf(mt1, fmaxf(sf[j][2], sf[j][3]));
        }
        mt0 = fmaxf(mt0, __shfl_xor_sync(0xffffffffu, mt0, 1));
        mt0 = fmaxf(mt0, __shfl_xor_sync(0xffffffffu, mt0, 2));
        mt1 = fmaxf(mt1, __shfl_xor_sync(0xffffffffu, mt1, 1));
        mt1 = fmaxf(mt1, __shfl_xor_sync(0xffffffffu, mt1, 2));
        float mn0 = fmaxf(m0, mt0), mn1 = fmaxf(m1, mt1);
        float a0 = __expf(m0 - mn0), a1 = __expf(m1 - mn1);
        float s0 = 0.f, s1 = 0.f;
#pragma unroll
        for (int j = 0; j < 8; j++) {
            sf[j][0] = __expf(sf[j][0] - mn0);
            sf[j][1] = __expf(sf[j][1] - mn0);
            sf[j][2] = __expf(sf[j][2] - mn1);
            sf[j][3] = __expf(sf[j][3] - mn1);
            s0 += sf[j][0] + sf[j][1];
            s1 += sf[j][2] + sf[j][3];
        }
        s0 += __shfl_xor_sync(0xffffffffu, s0, 1);
        s0 += __shfl_xor_sync(0xffffffffu, s0, 2);
        s1 += __shfl_xor_sync(0xffffffffu, s1, 1);
        s1 += __shfl_xor_sync(0xffffffffu, s1, 2);
        l0 = l0 * a0 + s0; l1 = l1 * a1 + s1;
        m0 = mn0; m1 = mn1;
#pragma unroll
        for (int i = 0; i < 16; i++) {
            of[i][0] *= a0; of[i][1] *= a0;
            of[i][2] *= a1; of[i][3] *= a1;
        }

#pragma unroll
        for (int c = 0; c < 4; c++) {
            uint32_t af[4];
            af[0] = pack_h2(sf[2 * c][0],     sf[2 * c][1]);
            af[1] = pack_h2(sf[2 * c][2],     sf[2 * c][3]);
            af[2] = pack_h2(sf[2 * c + 1][0], sf[2 * c + 1][1]);
            af[3] = pack_h2(sf[2 * c + 1][2], sf[2 * c + 1][3]);
#pragma unroll
            for (int d2 = 0; d2 < 8; d2++) {
                uint32_t vr[4];
                ldsm_x4t(vr, Vb + (16 * c + (lane & 15)) * AROW
                              + d2 * 32 + ((lane >> 4) & 1) * 16);
                mma16816(of[2 * d2],     af, vr);
                mma16816(of[2 * d2 + 1], af, vr + 2);
            }
        }
    }

    // write O (fp16) into the GEMM2 A operand [2048, 4096]
    const float inv0 = 1.f / l0, inv1 = 1.f / l1;
#pragma unroll
    for (int dt = 0; dt < 16; dt++) {
        int col = h * HD + dt * 8 + 2 * t4;
        *(__half2*)&g_A2[(size_t)row0 * KB + col] =
            __floats2half2_rn(of[dt][0] * inv0, of[dt][1] * inv0);
        *(__half2*)&g_A2[(size_t)(row0 + 8) * KB + col] =
            __floats2half2_rn(of[dt][2] * inv1, of[dt][3] * inv1);
    }
}

// ---------------------------------------------------------------------------
extern "C" void kernel_launch(void* const* d_in, const int* in_sizes, int n_in,
                              void* d_out, int out_size)
{
    const float* hidden    = (const float*)d_in[0];
    const float* Wqkv      = (const float*)d_in[1];
    const float* Wo        = (const float*)d_in[2];
    const int*   positions = (const int*)d_in[3];
    float*       out       = (float*)d_out;

    float* qkv_ptr;
    __half *A1, *A2, *Bqkv, *Bo;
    cudaGetSymbolAddress((void**)&qkv_ptr, g_qkv);
    cudaGetSymbolAddress((void**)&A1,   g_A1);
    cudaGetSymbolAddress((void**)&A2,   g_A2);
    cudaGetSymbolAddress((void**)&Bqkv, g_Bqkv);
    cudaGetSymbolAddress((void**)&Bo,   g_Bo);

    const int gemm_smem = STAGES * STAGE_BYTES;   // 110592
    cudaFuncSetAttribute(gemm_mma_kernel, cudaFuncAttributeMaxDynamicSharedMemorySize, gemm_smem);
    cudaFuncSetAttribute(attn_mma_kernel, cudaFuncAttributeMaxDynamicSharedMemorySize, ATTN_SMEM);

    // operand conversion (all hi-only)
    cvt_kernel<<<(SEQ * HIDDEN) / 256, 256>>>(hidden, A1, SEQ * HIDDEN);
    tsplit_kernel<<<dim3(QKVD / 32, HIDDEN / 32), dim3(32, 32)>>>(Wqkv, Bqkv, QKVD);
    tsplit_kernel<<<dim3(HIDDEN / 32, HIDDEN / 32), dim3(32, 32)>>>(Wo, Bo, HIDDEN);

    // 1) QKV projection (K = 4096, hi-only)
    gemm_mma_kernel<<<dim3(QKVD / 128, SEQ / 128), 256, gemm_smem>>>(A1, Bqkv, qkv_ptr, QKVD);
    // 2) fused RoPE + fp16 pack (q scaled)
    pack_rope_kernel<<<(SEQ * QKVD) / 256, 256>>>(positions);
    // 3) tensor-core flash attention -> g_A2 (fp16)
    attn_mma_kernel<<<dim3(SEQ / 128, NH), 256, ATTN_SMEM>>>();
    // 4) output projection (K = 4096, hi-only)
    gemm_mma_kernel<<<dim3(HIDDEN / 128, SEQ / 128), 256, gemm_smem>>>(A2, Bo, out, HIDDEN);
}

// round 13
// speedup vs baseline: 5.2461x; 1.0193x over previous
#include <cuda_runtime.h>
#include <cuda_fp16.h>
#include <cstdint>
#include <math.h>

#define SEQ    2048
#define HIDDEN 4096
#define NH     32
#define HD     128
#define NKV    8
#define QKVD   6144
#define KOFF   4096
#define VOFF   5120
#define KB     4096    // all GEMM operands: fp16 hi only, K = 4096
#define BK     64
#define STAGES 3
#define ROWB   144
#define STAGE_BYTES (128 * ROWB * 2)
#define B_OFF  (128 * ROWB)
// attention smem layout: Q + 3 KV buffers
#define AROW   272
#define Q_BYTES (128 * AROW)
#define KV_BYTES (64 * AROW)
#define ATTN_SMEM (Q_BYTES + 3 * (2 * KV_BYTES))  // 139264

// ---------------- scratch (__device__ globals; no allocs allowed) ----------
__device__ float  g_qkv [SEQ * QKVD];
__device__ __half g_A1  [SEQ * KB];        // hidden (hi)   [2048, 4096]
__device__ __half g_A2  [SEQ * KB];        // attn out (hi) [2048, 4096]
__device__ __half g_Bqkv[QKVD * KB];       // Wqkv^T hi     [6144, 4096]
__device__ __half g_Bo  [HIDDEN * KB];     // Wo^T   hi     [4096, 4096]
__device__ __half g_q16 [NH  * SEQ * HD];
__device__ __half g_k16 [NKV * SEQ * HD];
__device__ __half g_v16 [NKV * SEQ * HD];

__device__ __forceinline__ uint32_t smem_u32(const void* p) {
    uint32_t a;
    asm("{ .reg .u64 t; cvta.to.shared.u64 t, %1; cvt.u32.u64 %0, t; }" : "=r"(a) : "l"(p));
    return a;
}
#define CP_ASYNC16(dst, src) \
    asm volatile("cp.async.cg.shared.global [%0], [%1], 16;" :: "r"(dst), "l"(src) : "memory")

__device__ __forceinline__ void ldsm_x4(uint32_t* r, uint32_t addr) {
    asm volatile("ldmatrix.sync.aligned.m8n8.x4.shared.b16 {%0,%1,%2,%3}, [%4];"
                 : "=r"(r[0]), "=r"(r[1]), "=r"(r[2]), "=r"(r[3]) : "r"(addr));
}
__device__ __forceinline__ void ldsm_x4t(uint32_t* r, uint32_t addr) {
    asm volatile("ldmatrix.sync.aligned.m8n8.x4.trans.shared.b16 {%0,%1,%2,%3}, [%4];"
                 : "=r"(r[0]), "=r"(r[1]), "=r"(r[2]), "=r"(r[3]) : "r"(addr));
}
__device__ __forceinline__ void mma16816(float* d, const uint32_t* a, const uint32_t* b) {
    asm volatile(
        "mma.sync.aligned.m16n8k16.row.col.f32.f16.f16.f32 "
        "{%0,%1,%2,%3}, {%4,%5,%6,%7}, {%8,%9}, {%0,%1,%2,%3};"
        : "+f"(d[0]), "+f"(d[1]), "+f"(d[2]), "+f"(d[3])
        : "r"(a[0]), "r"(a[1]), "r"(a[2]), "r"(a[3]), "r"(b[0]), "r"(b[1]));
}
__device__ __forceinline__ uint32_t pack_h2(float a, float b) {
    __half2 h = __floats2half2_rn(a, b);
    return *(uint32_t*)&h;
}

// ---------------------------------------------------------------------------
// fp16 GEMM: C[M,N] = A[M,KB] @ Bt[N,KB]^T  (64 k-iterations)
// BM=BN=128, BK=64, 256 threads, 3-stage / lookahead-2 cp.async pipeline,
// ONE __syncthreads per iteration, 2 CTA/SM.
// ---------------------------------------------------------------------------
__global__ __launch_bounds__(256, 2) void gemm_mma_kernel(
    const __half* __restrict__ A,
    const __half* __restrict__ Bt,
    float* __restrict__ C, int N)
{
    extern __shared__ char smem[];
    const uint32_t sb = smem_u32(smem);
    const int tid = threadIdx.x;
    const int lane = tid & 31, warp = tid >> 5;
    const int wm = warp >> 2, wn = warp & 3;
    const int mbase = blockIdx.y * 128;
    const int nbase = blockIdx.x * 128;
    const int nIter = KB / BK;   // 64

    const __half* Arow = A  + (size_t)mbase * KB;
    const __half* Brow = Bt + (size_t)nbase * KB;

    const int c_row = tid >> 1;
    const int c_ch0 = (tid & 1) * 4;

    auto load_stage = [&](int itL, int stL) {
        const int kb = itL * BK;
        const uint32_t base = sb + stL * STAGE_BYTES;
        const char* asrc = (const char*)(Arow + (size_t)c_row * KB + kb);
        const char* bsrc = (const char*)(Brow + (size_t)c_row * KB + kb);
#pragma unroll
        for (int c = 0; c < 4; c++) {
            int ch = c_ch0 + c;
            CP_ASYNC16(base + c_row * ROWB + ch * 16,         asrc + ch * 16);
            CP_ASYNC16(base + B_OFF + c_row * ROWB + ch * 16, bsrc + ch * 16);
        }
    };

    float acc[4][4][4];
#pragma unroll
    for (int i = 0; i < 4; i++)
#pragma unroll
        for (int j = 0; j < 4; j++)
#pragma unroll
            for (int r = 0; r < 4; r++) acc[i][j][r] = 0.f;

    // prologue: tiles 0 and 1 (lookahead-2)
    load_stage(0, 0);
    asm volatile("cp.async.commit_group;" ::: "memory");
    load_stage(1, 1);
    asm volatile("cp.async.commit_group;" ::: "memory");

    const uint32_t a_row = wm * 64 + (lane & 15);
    const uint32_t a_kc  = (lane >> 4);
    const uint32_t b_row0 = wn * 32 + (lane & 7);
    const uint32_t b_half = (lane >> 4) & 1;
    const uint32_t b_kc   = (lane >> 3) & 1;

    for (int it = 0; it < nIter; it++) {
        const int st = it % 3;
        if (it < nIter - 1) asm volatile("cp.async.wait_group 1;" ::: "memory");
        else                asm volatile("cp.async.wait_group 0;" ::: "memory");
        __syncthreads();
        // prefetch tile it+2 into stage (it+2)%3 (consumed at iter it-1;
        // the barrier above orders all its readers before these writes)
        if (it + 2 < nIter) {
            load_stage(it + 2, (it + 2) % 3);
            asm volatile("cp.async.commit_group;" ::: "memory");
        }

        const uint32_t abase = sb + st * STAGE_BYTES;
        const uint32_t bbase = abase + B_OFF;

#pragma unroll
        for (int s = 0; s < 4; s++) {
            uint32_t af[4][4];
#pragma unroll
            for (int i = 0; i < 4; i++)
                ldsm_x4(af[i], abase + (a_row + i * 16) * ROWB + (s * 2 + a_kc) * 16);
            uint32_t bf[4][2];
#pragma unroll
            for (int jj = 0; jj < 2; jj++) {
                uint32_t r[4];
                uint32_t brow = b_row0 + (2 * jj + b_half) * 8;
                ldsm_x4(r, bbase + brow * ROWB + (s * 2 + b_kc) * 16);
                bf[2 * jj][0] = r[0]; bf[2 * jj][1] = r[1];
                bf[2 * jj + 1][0] = r[2]; bf[2 * jj + 1][1] = r[3];
            }
#pragma unroll
            for (int i = 0; i < 4; i++)
#pragma unroll
                for (int j = 0; j < 4; j++)
                    mma16816(acc[i][j], af[i], bf[j]);
        }
    }

    const int g = lane >> 2, t = lane & 3;
#pragma unroll
    for (int i = 0; i < 4; i++) {
#pragma unroll
        for (int j = 0; j < 4; j++) {
            int row = mbase + wm * 64 + i * 16 + g;
            int col = nbase + wn * 32 + j * 8 + 2 * t;
            *(float2*)&C[(size_t)row * N + col] =
                make_float2(acc[i][j][0], acc[i][j][1]);
            *(float2*)&C[(size_t)(row + 8) * N + col] =
                make_float2(acc[i][j][2], acc[i][j][3]);
        }
    }
}

// ---------------------------------------------------------------------------
// fp32 -> fp16 convert (hi only): X[M,4096] -> Y[M,4096]
// ---------------------------------------------------------------------------
__global__ __launch_bounds__(256) void cvt_kernel(
    const float* __restrict__ X, __half* __restrict__ Y, int total)
{
    int idx = blockIdx.x * blockDim.x + threadIdx.x;
    if (idx >= total) return;
    Y[idx] = __float2half(X[idx]);
}

// ---------------------------------------------------------------------------
// W [4096, N] -> Bt [N, 4096] fp16 hi, tiled transpose.
// ---------------------------------------------------------------------------
__global__ __launch_bounds__(1024) void tsplit_kernel(
    const float* __restrict__ W, __half* __restrict__ Bt, int N)
{
    __shared__ float t[32][33];
    int n0 = blockIdx.x * 32, k0 = blockIdx.y * 32;
    t[threadIdx.y][threadIdx.x] = W[(size_t)(k0 + threadIdx.y) * N + n0 + threadIdx.x];
    __syncthreads();
    float x = t[threadIdx.x][threadIdx.y];
    int n = n0 + threadIdx.y, k = k0 + threadIdx.x;
    Bt[(size_t)n * KB + k] = __float2half(x);
}

// ---------------------------------------------------------------------------
// Fused RoPE + fp16 pack: g_qkv -> g_q16/g_k16/g_v16 (Q gets 1/sqrt(HD)).
// ---------------------------------------------------------------------------
__global__ __launch_bounds__(256) void pack_rope_kernel(const int* __restrict__ pos32)
{
    int idx = blockIdx.x * blockDim.x + threadIdx.x;
    if (idx >= SEQ * QKVD) return;
    int d  = idx & 127;
    int hh = (idx >> 7) % 48;
    int s  = idx / QKVD;

    if (hh < 40) {
        int base = s * QKVD + ((hh < 32) ? hh * HD : KOFF + (hh - 32) * HD);
        float v;
        if (d < 64) {
            int j = d & 31;
            bool is64 = (pos32[1] == 0);
            int posi = is64 ? pos32[2 * s] : pos32[s];
            float inv_freq = 1.0f / powf(10000.0f, (float)j * (1.0f / 32.0f));
            float fr = (float)posi * inv_freq;
            float cs, sn;
            sincosf(fr, &sn, &cs);
            float x1 = g_qkv[base + j];
            float x2 = g_qkv[base + 32 + j];
            v = (d < 32) ? (x1 * cs - x2 * sn) : (x2 * cs + x1 * sn);
        } else {
            v = g_qkv[base + d];
        }
        if (hh < 32)
            g_q16[((size_t)hh * SEQ + s) * HD + d] = __float2half(v * 0.088388347648318447f);
        else
            g_k16[((size_t)(hh - 32) * SEQ + s) * HD + d] = __float2half(v);
    } else {
        int kvh = hh - 40;
        float v = g_qkv[s * QKVD + VOFF + kvh * HD + d];
        g_v16[((size_t)kvh * SEQ + s) * HD + d] = __float2half(v);
    }
}

// ---------------------------------------------------------------------------
// Flash attention on mma.sync fp16. CTA = (128 q-rows, head); 8 warps x 16
// rows; 3 KV buffers, lookahead-2, ONE __syncthreads per KV tile.
// Output: fp16 into g_A2.
// ---------------------------------------------------------------------------
__global__ __launch_bounds__(256) void attn_mma_kernel()
{
    extern __shared__ char smem[];
    const uint32_t sb = smem_u32(smem);
    const uint32_t Qs = sb;
    const int tid = threadIdx.x, lane = tid & 31, warp = tid >> 5;
    const int g = lane >> 2, t4 = lane & 3;
    const int qt = gridDim.x - 1 - (int)blockIdx.x;
    const int h = blockIdx.y, kvh = h >> 2;
    const int qbase = qt * 128;
    const int qrw = warp * 16;
    const int ntiles = qt * 2 + 2;

    const __half* q16 = g_q16 + (size_t)h   * SEQ * HD;
    const __half* k16 = g_k16 + (size_t)kvh * SEQ * HD;
    const __half* v16 = g_v16 + (size_t)kvh * SEQ * HD;

    auto load_kv = [&](int tt) {
        const int buf = tt % 3;
        const uint32_t Kb = sb + Q_BYTES + buf * (2 * KV_BYTES);
        const uint32_t Vb = Kb + KV_BYTES;
        const int kb = tt * 64;
#pragma unroll
        for (int i = 0; i < 4; i++) {
            int c = tid + 256 * i;
            int row = c >> 4, ch = c & 15;
            CP_ASYNC16(Kb + row * AROW + ch * 16,
                       (const char*)(k16 + (size_t)(kb + row) * HD) + ch * 16);
            CP_ASYNC16(Vb + row * AROW + ch * 16,
                       (const char*)(v16 + (size_t)(kb + row) * HD) + ch * 16);
        }
    };

    // prologue: Q tile + KV tile 0 (group 0), KV tile 1 (group 1)
#pragma unroll
    for (int i = 0; i < 8; i++) {
        int c = tid + 256 * i;
        int row = c >> 4, ch = c & 15;
        CP_ASYNC16(Qs + row * AROW + ch * 16,
                   (const char*)(q16 + (size_t)(qbase + row) * HD) + ch * 16);
    }
    load_kv(0);
    asm volatile("cp.async.commit_group;" ::: "memory");
    load_kv(1);
    asm volatile("cp.async.commit_group;" ::: "memory");

    float of[16][4];
#pragma unroll
    for (int i = 0; i < 16; i++)
#pragma unroll
        for (int r = 0; r < 4; r++) of[i][r] = 0.f;
    float m0 = -INFINITY, m1 = -INFINITY, l0 = 0.f, l1 = 0.f;

    const int row0 = qbase + qrw + g;

    for (int tt = 0; tt < ntiles; tt++) {
        if (tt < ntiles - 1) asm volatile("cp.async.wait_group 1;" ::: "memory");
        else                 asm volatile("cp.async.wait_group 0;" ::: "memory");
        __syncthreads();
        // prefetch tile tt+2 into buffer (tt+2)%3 (consumed at tile tt-1)
        if (tt + 2 < ntiles) {
            load_kv(tt + 2);
            asm volatile("cp.async.commit_group;" ::: "memory");
        }

        const int kb = tt * 64;
        const uint32_t Kb = sb + Q_BYTES + (tt % 3) * (2 * KV_BYTES);
        const uint32_t Vb = Kb + KV_BYTES;

        float sf[8][4];
#pragma unroll
        for (int j = 0; j < 8; j++)
#pragma unroll
            for (int r = 0; r < 4; r++) sf[j][r] = 0.f;
#pragma unroll
        for (int s = 0; s < 8; s++) {
            uint32_t qf[4];
            ldsm_x4(qf, Qs + (qrw + (lane & 15)) * AROW + (s * 2 + (lane >> 4)) * 16);
#pragma unroll
            for (int jj = 0; jj < 4; jj++) {
                uint32_t kr[4];
                int brow = (lane & 7) + (2 * jj + ((lane >> 4) & 1)) * 8;
                ldsm_x4(kr, Kb + brow * AROW + (s * 2 + ((lane >> 3) & 1)) * 16);
                mma16816(sf[2 * jj],     qf, kr);
                mma16816(sf[2 * jj + 1], qf, kr + 2);
            }
        }

        // causal mask — needed whenever max col of tile exceeds MIN row of strip
        if (kb + 63 > qbase + qrw) {
#pragma unroll
            for (int j = 0; j < 8; j++) {
                int c0 = kb + j * 8 + 2 * t4;
                if (c0     > row0)     sf[j][0] = -INFINITY;
                if (c0 + 1 > row0)     sf[j][1] = -INFINITY;
                if (c0     > row0 + 8) sf[j][2] = -INFINITY;
                if (c0 + 1 > row0 + 8) sf[j][3] = -INFINITY;
            }
        }

        float mt0 = -INFINITY, mt1 = -INFINITY;
#pragma unroll
        for (int j = 0; j < 8; j++) {
            mt0 = fmaxf(mt0, fmaxf(sf[j][0], sf[j][1]));
            mt1 = fmaxf(mt1, fmaxf(sf[j][2], sf[j][3]));
        }
        mt0 = fmaxf(mt0, __shfl_xor_sync(0xffffffffu, mt0, 1));
        mt0 = fmaxf(mt0, __shfl_xor_sync(0xffffffffu, mt0, 2));
        mt1 = fmaxf(mt1, __shfl_xor_sync(0xffffffffu, mt1, 1));
        mt1 = fmaxf(mt1, __shfl_xor_sync(0xffffffffu, mt1, 2));
        float mn0 = fmaxf(m0, mt0), mn1 = fmaxf(m1, mt1);
        float a0 = __expf(m0 - mn0), a1 = __expf(m1 - mn1);
        float s0 = 0.f, s1 = 0.f;
#pragma unroll
        for (int j = 0; j < 8; j++) {
            sf[j][0] = __expf(sf[j][0] - mn0);
            sf[j][1] = __expf(sf[j][1] - mn0);
            sf[j][2] = __expf(sf[j][2] - mn1);
            sf[j][3] = __expf(sf[j][3] - mn1);
            s0 += sf[j][0] + sf[j][1];
            s1 += sf[j][2] + sf[j][3];
        }
        s0 += __shfl_xor_sync(0xffffffffu, s0, 1);
        s0 += __shfl_xor_sync(0xffffffffu, s0, 2);
        s1 += __shfl_xor_sync(0xffffffffu, s1, 1);
        s1 += __shfl_xor_sync(0xffffffffu, s1, 2);
        l0 = l0 * a0 + s0; l1 = l1 * a1 + s1;
        m0 = mn0; m1 = mn1;
#pragma unroll
        for (int i = 0; i < 16; i++) {
            of[i][0] *= a0; of[i][1] *= a0;
            of[i][2] *= a1; of[i][3] *= a1;
        }

#pragma unroll
        for (int c = 0; c < 4; c++) {
            uint32_t af[4];
            af[0] = pack_h2(sf[2 * c][0],     sf[2 * c][1]);
            af[1] = pack_h2(sf[2 * c][2],     sf[2 * c][3]);
            af[2] = pack_h2(sf[2 * c + 1][0], sf[2 * c + 1][1]);
            af[3] = pack_h2(sf[2 * c + 1][2], sf[2 * c + 1][3]);
#pragma unroll
            for (int d2 = 0; d2 < 8; d2++) {
                uint32_t vr[4];
                ldsm_x4t(vr, Vb + (16 * c + (lane & 15)) * AROW
                              + d2 * 32 + ((lane >> 4) & 1) * 16);
                mma16816(of[2 * d2],     af, vr);
                mma16816(of[2 * d2 + 1], af, vr + 2);
            }
        }
    }

    // write O (fp16) into the GEMM2 A operand [2048, 4096]
    const float inv0 = 1.f / l0, inv1 = 1.f / l1;
#pragma unroll
    for (int dt = 0; dt < 16; dt++) {
        int col = h * HD + dt * 8 + 2 * t4;
        *(__half2*)&g_A2[(size_t)row0 * KB + col] =
            __floats2half2_rn(of[dt][0] * inv0, of[dt][1] * inv0);
        *(__half2*)&g_A2[(size_t)(row0 + 8) * KB + col] =
            __floats2half2_rn(of[dt][2] * inv1, of[dt][3] * inv1);
    }
}

// ---------------------------------------------------------------------------
extern "C" void kernel_launch(void* const* d_in, const int* in_sizes, int n_in,
                              void* d_out, int out_size)
{
    const float* hidden    = (const float*)d_in[0];
    const float* Wqkv      = (const float*)d_in[1];
    const float* Wo        = (const float*)d_in[2];
    const int*   positions = (const int*)d_in[3];
    float*       out       = (float*)d_out;

    float* qkv_ptr;
    __half *A1, *A2, *Bqkv, *Bo;
    cudaGetSymbolAddress((void**)&qkv_ptr, g_qkv);
    cudaGetSymbolAddress((void**)&A1,   g_A1);
    cudaGetSymbolAddress((void**)&A2,   g_A2);
    cudaGetSymbolAddress((void**)&Bqkv, g_Bqkv);
    cudaGetSymbolAddress((void**)&Bo,   g_Bo);

    const int gemm_smem = STAGES * STAGE_BYTES;   // 110592
    cudaFuncSetAttribute(gemm_mma_kernel, cudaFuncAttributeMaxDynamicSharedMemorySize, gemm_smem);
    cudaFuncSetAttribute(attn_mma_kernel, cudaFuncAttributeMaxDynamicSharedMemorySize, ATTN_SMEM);

    // operand conversion (all hi-only)
    cvt_kernel<<<(SEQ * HIDDEN) / 256, 256>>>(hidden, A1, SEQ * HIDDEN);
    tsplit_kernel<<<dim3(QKVD / 32, HIDDEN / 32), dim3(32, 32)>>>(Wqkv, Bqkv, QKVD);
    tsplit_kernel<<<dim3(HIDDEN / 32, HIDDEN / 32), dim3(32, 32)>>>(Wo, Bo, HIDDEN);

    // 1) QKV projection (K = 4096)
    gemm_mma_kernel<<<dim3(QKVD / 128, SEQ / 128), 256, gemm_smem>>>(A1, Bqkv, qkv_ptr, QKVD);
    // 2) fused RoPE + fp16 pack (q scaled)
    pack_rope_kernel<<<(SEQ * QKVD) / 256, 256>>>(positions);
    // 3) tensor-core flash attention -> g_A2 (fp16)
    attn_mma_kernel<<<dim3(SEQ / 128, NH), 256, ATTN_SMEM>>>();
    // 4) output projection (K = 4096)
    gemm_mma_kernel<<<dim3(HIDDEN / 128, SEQ / 128), 256, gemm_smem>>>(A2, Bo, out, HIDDEN);
}